// round 7
// baseline (speedup 1.0000x reference)
#include <cuda_runtime.h>
#include <cuda_bf16.h>
#include <math.h>
#include <stdint.h>

// ---------------- problem constants ----------------
#define BATCH   2
#define SEQLEN  2048
#define DMODEL  4096
#define NHEADS  32
#define NKV     8
#define HD      128
#define QDIM    (NHEADS * HD)            // 4096
#define KVDIM   (NKV * HD)               // 1024
#define QKVDIM  (QDIM + 2 * KVDIM)       // 6144
#define MROWS   (BATCH * SEQLEN)         // 4096

// ---------------- scratch (device globals: allocation-free) ----------------
__device__ float g_qkv[(size_t)MROWS * QKVDIM];
__device__ __nv_bfloat16 g_xh[(size_t)MROWS * DMODEL];
__device__ __nv_bfloat16 g_xl[(size_t)MROWS * DMODEL];
__device__ __nv_bfloat16 g_wqkvh[(size_t)QKVDIM * DMODEL];
__device__ __nv_bfloat16 g_wqkvl[(size_t)QKVDIM * DMODEL];
__device__ __nv_bfloat16 g_woh[(size_t)DMODEL * DMODEL];
__device__ __nv_bfloat16 g_wol[(size_t)DMODEL * DMODEL];
__device__ __nv_bfloat16 g_ah[(size_t)MROWS * DMODEL];
__device__ __nv_bfloat16 g_al[(size_t)MROWS * DMODEL];
__device__ __nv_bfloat16 g_qh[(size_t)MROWS * QKVDIM];
__device__ __nv_bfloat16 g_ql[(size_t)MROWS * QKVDIM];

// ---------------- helpers ----------------
__device__ __forceinline__ uint32_t smem_to_u32(const void* smem_ptr) {
    uint32_t addr;
    asm("{ .reg .u64 tmp; cvta.to.shared.u64 tmp, %1; cvt.u32.u64 %0, tmp; }"
        : "=r"(addr) : "l"(smem_ptr));
    return addr;
}
__device__ __forceinline__ void cp_async16(uint32_t dst, const void* src) {
    asm volatile("cp.async.cg.shared.global [%0], [%1], 16;\n"
                 :: "r"(dst), "l"(src));
}
__device__ __forceinline__ void cp_commit() {
    asm volatile("cp.async.commit_group;\n" ::: "memory");
}
__device__ __forceinline__ void cp_wait1() {
    asm volatile("cp.async.wait_group 1;\n" ::: "memory");
}
__device__ __forceinline__ void cp_wait2() {
    asm volatile("cp.async.wait_group 2;\n" ::: "memory");
}
__device__ __forceinline__ void ldm_x4(uint32_t* r, uint32_t a) {
    asm volatile("ldmatrix.sync.aligned.m8n8.x4.shared.b16 {%0,%1,%2,%3}, [%4];"
                 : "=r"(r[0]), "=r"(r[1]), "=r"(r[2]), "=r"(r[3]) : "r"(a));
}
__device__ __forceinline__ void ldm_x4_t(uint32_t* r, uint32_t a) {
    asm volatile("ldmatrix.sync.aligned.m8n8.x4.trans.shared.b16 {%0,%1,%2,%3}, [%4];"
                 : "=r"(r[0]), "=r"(r[1]), "=r"(r[2]), "=r"(r[3]) : "r"(a));
}
__device__ __forceinline__ void mma_bf16(float* c, const uint32_t* a,
                                         uint32_t b0, uint32_t b1) {
    asm volatile(
        "mma.sync.aligned.m16n8k16.row.col.f32.bf16.bf16.f32 "
        "{%0,%1,%2,%3}, {%4,%5,%6,%7}, {%8,%9}, {%0,%1,%2,%3};"
        : "+f"(c[0]), "+f"(c[1]), "+f"(c[2]), "+f"(c[3])
        : "r"(a[0]), "r"(a[1]), "r"(a[2]), "r"(a[3]), "r"(b0), "r"(b1));
}
__device__ __forceinline__ float ex2f(float x) {
    float y;
    asm("ex2.approx.f32 %0, %1;" : "=f"(y) : "f"(x));
    return y;
}
__device__ __forceinline__ uint32_t pack_bf16(float f0, float f1) {
    uint16_t b0 = __bfloat16_as_ushort(__float2bfloat16_rn(f0));
    uint16_t b1 = __bfloat16_as_ushort(__float2bfloat16_rn(f1));
    return ((uint32_t)b1 << 16) | (uint32_t)b0;
}

// ============================================================
// HMMA GEMM v2: 512 threads (16 warps, warp tile 64x32),
// CTA tile 128x256, BK=32, 3-stage cp.async pipeline,
// bf16x3 emulation, fp32 accum.
// ============================================================
#define HBM 128
#define HBN 256
#define HBK 32
#define ROWB 80
#define OFF_AH 0
#define OFF_AL 10240
#define OFF_BH 20480
#define OFF_BL 40960
#define STAGE_B 61440
#define HSMEM (3 * STAGE_B)      // 184320 bytes

__device__ __forceinline__ void gemm_load_stage(
    const __nv_bfloat16* __restrict__ Ah, const __nv_bfloat16* __restrict__ Al,
    const __nv_bfloat16* __restrict__ Bh, const __nv_bfloat16* __restrict__ Bl,
    uint32_t sbase, int bm, int bn, int k0, int K, int tid)
{
    // A: 128 rows x 4 chunks x 2 halves = 1024 chunks; 512 threads -> 2 iters
    #pragma unroll
    for (int l = 0; l < 2; l++) {
        int u = tid + l * 512;
        int half = u >> 9;
        int r = (u >> 2) & 127, g = u & 3;
        size_t goff = (size_t)(bm + r) * K + k0 + g * 8;
        cp_async16(sbase + (half ? OFF_AL : OFF_AH) + r * ROWB + g * 16,
                   (half ? Al : Ah) + goff);
    }
    // B: 256 rows x 4 chunks x 2 halves = 2048 chunks; -> 4 iters
    #pragma unroll
    for (int l = 0; l < 4; l++) {
        int u = tid + l * 512;
        int half = u >> 10;
        int r = (u >> 2) & 255, g = u & 3;
        size_t goff = (size_t)(bn + r) * K + k0 + g * 8;
        cp_async16(sbase + (half ? OFF_BL : OFF_BH) + r * ROWB + g * 16,
                   (half ? Bl : Bh) + goff);
    }
}

__global__ __launch_bounds__(512, 1) void hmma_gemm_kernel(
    const __nv_bfloat16* __restrict__ Ah, const __nv_bfloat16* __restrict__ Al,
    const __nv_bfloat16* __restrict__ Bh, const __nv_bfloat16* __restrict__ Bl,
    const float* __restrict__ bias, float* __restrict__ C,
    int M, int N, int K)
{
    extern __shared__ char smem[];
    const uint32_t sb = smem_to_u32(smem);
    const int tid = threadIdx.x;
    const int lane = tid & 31, wid = tid >> 5;
    const int wm = wid & 1;        // 2 warp rows (64 m each)
    const int wn = wid >> 1;       // 8 warp cols (32 n each)
    const int bm = blockIdx.y * HBM;
    const int bn = blockIdx.x * HBN;

    float acc[4][4][4];
    #pragma unroll
    for (int i = 0; i < 4; i++)
        #pragma unroll
        for (int j = 0; j < 4; j++)
            #pragma unroll
            for (int v = 0; v < 4; v++) acc[i][j][v] = 0.f;

    const int NC = K / HBK;

    gemm_load_stage(Ah, Al, Bh, Bl, sb, bm, bn, 0, K, tid);
    cp_commit();
    gemm_load_stage(Ah, Al, Bh, Bl, sb + STAGE_B, bm, bn, HBK, K, tid);
    cp_commit();

    int st = 0;   // stage index of chunk c
    for (int c = 0; c < NC; c++) {
        if (c + 2 < NC) {
            int st2 = st + 2; if (st2 >= 3) st2 -= 3;
            gemm_load_stage(Ah, Al, Bh, Bl, sb + st2 * STAGE_B,
                            bm, bn, (c + 2) * HBK, K, tid);
        }
        cp_commit();
        cp_wait2();
        __syncthreads();

        const uint32_t base = sb + st * STAGE_B;
        #pragma unroll
        for (int ks = 0; ks < 2; ks++) {
            const int kb = ks * 32 + ((lane >> 4) * 16);
            uint32_t a_addr = base + OFF_AH + (wm * 64 + (lane & 15)) * ROWB + kb;
            uint32_t b_addr = base + OFF_BH + (wn * 32 + (lane & 15)) * ROWB + kb;

            uint32_t A0[4][4], A1[4][4], B0[2][4];
            #pragma unroll
            for (int mt = 0; mt < 4; mt++) ldm_x4(A0[mt], a_addr + mt * 16 * ROWB);
            #pragma unroll
            for (int nb = 0; nb < 2; nb++) ldm_x4(B0[nb], b_addr + nb * 16 * ROWB);

            // pass 1: Ah * Bh
            #pragma unroll
            for (int mt = 0; mt < 4; mt++)
                #pragma unroll
                for (int nb = 0; nb < 2; nb++) {
                    mma_bf16(acc[mt][2 * nb],     A0[mt], B0[nb][0], B0[nb][2]);
                    mma_bf16(acc[mt][2 * nb + 1], A0[mt], B0[nb][1], B0[nb][3]);
                }
            // pass 2: Al * Bh
            #pragma unroll
            for (int mt = 0; mt < 4; mt++)
                ldm_x4(A1[mt], a_addr + (OFF_AL - OFF_AH) + mt * 16 * ROWB);
            #pragma unroll
            for (int mt = 0; mt < 4; mt++)
                #pragma unroll
                for (int nb = 0; nb < 2; nb++) {
                    mma_bf16(acc[mt][2 * nb],     A1[mt], B0[nb][0], B0[nb][2]);
                    mma_bf16(acc[mt][2 * nb + 1], A1[mt], B0[nb][1], B0[nb][3]);
                }
            // pass 3: Ah * Bl
            #pragma unroll
            for (int nb = 0; nb < 2; nb++)
                ldm_x4(B0[nb], b_addr + (OFF_BL - OFF_BH) + nb * 16 * ROWB);
            #pragma unroll
            for (int mt = 0; mt < 4; mt++)
                #pragma unroll
                for (int nb = 0; nb < 2; nb++) {
                    mma_bf16(acc[mt][2 * nb],     A0[mt], B0[nb][0], B0[nb][2]);
                    mma_bf16(acc[mt][2 * nb + 1], A0[mt], B0[nb][1], B0[nb][3]);
                }
        }
        __syncthreads();
        if (++st == 3) st = 0;
    }

    // epilogue: fused bias, float2 stores
    #pragma unroll
    for (int mt = 0; mt < 4; mt++) {
        const int row0 = bm + wm * 64 + mt * 16 + (lane >> 2);
        #pragma unroll
        for (int nt = 0; nt < 4; nt++) {
            const int col = bn + wn * 32 + nt * 8 + (lane & 3) * 2;
            const float b0 = bias[col], b1 = bias[col + 1];
            float2 v0 = make_float2(acc[mt][nt][0] + b0, acc[mt][nt][1] + b1);
            float2 v1 = make_float2(acc[mt][nt][2] + b0, acc[mt][nt][3] + b1);
            *(float2*)(C + (size_t)row0 * N + col) = v0;
            *(float2*)(C + (size_t)(row0 + 8) * N + col) = v1;
        }
    }
}

// ============================================================
// fp32 -> bf16 hi/lo split (for x, weights)
// ============================================================
__global__ void split_bf16_kernel(const float* __restrict__ src,
                                  __nv_bfloat16* __restrict__ hi,
                                  __nv_bfloat16* __restrict__ lo, int n4)
{
    int i = blockIdx.x * blockDim.x + threadIdx.x;
    if (i >= n4) return;
    float4 v = ((const float4*)src)[i];
    __nv_bfloat16 h0 = __float2bfloat16(v.x);
    __nv_bfloat16 h1 = __float2bfloat16(v.y);
    __nv_bfloat16 h2 = __float2bfloat16(v.z);
    __nv_bfloat16 h3 = __float2bfloat16(v.w);
    __nv_bfloat16 l0 = __float2bfloat16(v.x - __bfloat162float(h0));
    __nv_bfloat16 l1 = __float2bfloat16(v.y - __bfloat162float(h1));
    __nv_bfloat16 l2 = __float2bfloat16(v.z - __bfloat162float(h2));
    __nv_bfloat16 l3 = __float2bfloat16(v.w - __bfloat162float(h3));
    __nv_bfloat162* hp = (__nv_bfloat162*)hi;
    __nv_bfloat162* lp = (__nv_bfloat162*)lo;
    hp[2 * i]     = __nv_bfloat162(h0, h1);
    hp[2 * i + 1] = __nv_bfloat162(h2, h3);
    lp[2 * i]     = __nv_bfloat162(l0, l1);
    lp[2 * i + 1] = __nv_bfloat162(l2, l3);
}

// ============================================================
// RoPE+split on q/k: one thread per (row, freq-pair) -> 40 heads
// ============================================================
__global__ void rope_split_qk_kernel(const float* __restrict__ qkv,
                                     __nv_bfloat16* __restrict__ oh,
                                     __nv_bfloat16* __restrict__ ol)
{
    int idx = blockIdx.x * blockDim.x + threadIdx.x;   // MROWS*64
    int p = idx & 63;
    int rowi = idx >> 6;
    if (rowi >= MROWS) return;
    int s = rowi & (SEQLEN - 1);

    float inv_freq = powf(10000.0f, -(float)(2 * p) / (float)HD);
    float ang = (float)s * inv_freq;
    float c, sn;
    sincosf(ang, &sn, &c);

    const float* row = qkv + (size_t)rowi * QKVDIM;
    __nv_bfloat16* ohr = oh + (size_t)rowi * QKVDIM;
    __nv_bfloat16* olr = ol + (size_t)rowi * QKVDIM;

    #pragma unroll 4
    for (int hh = 0; hh < NHEADS + NKV; hh++) {
        int col = ((hh < NHEADS) ? hh * HD : QDIM + (hh - NHEADS) * HD) + 2 * p;
        float2 v = *(const float2*)(row + col);
        float r0 = v.x * c - v.y * sn;
        float r1 = v.x * sn + v.y * c;
        __nv_bfloat16 h0 = __float2bfloat16(r0);
        __nv_bfloat16 h1 = __float2bfloat16(r1);
        __nv_bfloat16 l0 = __float2bfloat16(r0 - __bfloat162float(h0));
        __nv_bfloat16 l1 = __float2bfloat16(r1 - __bfloat162float(h1));
        *(__nv_bfloat162*)(ohr + col) = __nv_bfloat162(h0, h1);
        *(__nv_bfloat162*)(olr + col) = __nv_bfloat162(l0, l1);
    }
}

// split-only for V region (cols QDIM+KVDIM .. QKVDIM)
__global__ void split_v_kernel(const float* __restrict__ qkv,
                               __nv_bfloat16* __restrict__ oh,
                               __nv_bfloat16* __restrict__ ol)
{
    int idx = blockIdx.x * blockDim.x + threadIdx.x;   // MROWS*512 pairs
    int c2 = idx & 511;
    int rowi = idx >> 9;
    if (rowi >= MROWS) return;
    size_t off = (size_t)rowi * QKVDIM + QDIM + KVDIM + 2 * c2;
    float2 v = *(const float2*)(g_qkv + off);
    (void)qkv;
    __nv_bfloat16 h0 = __float2bfloat16(v.x);
    __nv_bfloat16 h1 = __float2bfloat16(v.y);
    __nv_bfloat16 l0 = __float2bfloat16(v.x - __bfloat162float(h0));
    __nv_bfloat16 l1 = __float2bfloat16(v.y - __bfloat162float(h1));
    *(__nv_bfloat162*)(oh + off) = __nv_bfloat162(h0, h1);
    *(__nv_bfloat162*)(ol + off) = __nv_bfloat162(l0, l1);
}

// ============================================================
// HMMA flash attention (unchanged from round 5, passing):
// Br=128 (8 warps x 16 rows), Bc=64, bf16x3 for QK^T and PV.
// ============================================================
#define QROWB 272
#define FA_QH  0
#define FA_QL  34816
#define FA_ST0 69632
#define FA_STB 69632
#define FA_KH  0
#define FA_KL  17408
#define FA_VH  34816
#define FA_VL  52224
#define FA_SMEM (69632 + 2 * 69632)

__global__ __launch_bounds__(256) void fa_hmma_kernel(
    const __nv_bfloat16* __restrict__ qh, const __nv_bfloat16* __restrict__ ql,
    __nv_bfloat16* __restrict__ oh, __nv_bfloat16* __restrict__ ol)
{
    extern __shared__ char smem[];
    const uint32_t sb = smem_to_u32(smem);
    const int tid = threadIdx.x;
    const int lane = tid & 31, w = tid >> 5;
    const int b = blockIdx.z, h = blockIdx.y, qb = blockIdx.x;
    const int kvh = h >> 2;
    const int q0 = qb * 128;
    const int rowbase = b * SEQLEN;

    #pragma unroll
    for (int l = 0; l < 16; l++) {
        int u = tid + l * 256;
        int half = u >> 11;
        int r = (u >> 4) & 127;
        int ch = u & 15;
        const __nv_bfloat16* src = (half ? ql : qh) +
            (size_t)(rowbase + q0 + r) * QKVDIM + h * HD + ch * 8;
        cp_async16(sb + (half ? FA_QL : FA_QH) + r * QROWB + ch * 16, src);
    }
    auto load_kv = [&](int t, int s) {
        const int k0 = t * 64;
        const uint32_t stb = sb + FA_ST0 + s * FA_STB;
        #pragma unroll
        for (int l = 0; l < 16; l++) {
            int u = tid + l * 256;
            int sel = u >> 10;
            int r = (u >> 4) & 63;
            int ch = u & 15;
            int gcol = (sel < 2) ? (QDIM + kvh * HD) : (QDIM + KVDIM + kvh * HD);
            const __nv_bfloat16* base = (sel & 1) ? ql : qh;
            const __nv_bfloat16* src = base +
                (size_t)(rowbase + k0 + r) * QKVDIM + gcol + ch * 8;
            cp_async16(stb + sel * 17408 + r * QROWB + ch * 16, src);
        }
    };

    const int tmax = 2 * qb + 2;
    load_kv(0, 0);
    cp_commit();

    const float CEXP = 0.12751742f;
    float m2[2] = {-1e30f, -1e30f};
    float l2[2] = {0.f, 0.f};
    float O[16][4];
    #pragma unroll
    for (int i = 0; i < 16; i++)
        #pragma unroll
        for (int v = 0; v < 4; v++) O[i][v] = 0.f;

    const int qrow0 = q0 + w * 16;

    for (int t = 0; t < tmax; t++) {
        if (t + 1 < tmax) load_kv(t + 1, (t + 1) & 1);
        cp_commit();
        cp_wait1();
        __syncthreads();

        const int k0 = t * 64;
        const uint32_t stb = sb + FA_ST0 + (t & 1) * FA_STB;

        if (k0 <= qrow0 + 15) {
            float S[8][4];
            #pragma unroll
            for (int i = 0; i < 8; i++)
                #pragma unroll
                for (int v = 0; v < 4; v++) S[i][v] = 0.f;

            const uint32_t qa = sb + FA_QH + (w * 16 + (lane & 15)) * QROWB +
                                ((lane >> 4) * 16);
            const uint32_t ka = stb + FA_KH + ((lane & 15)) * QROWB +
                                ((lane >> 4) * 16);
            #pragma unroll
            for (int kc = 0; kc < 8; kc++) {
                uint32_t A0[4], A1[4];
                ldm_x4(A0, qa + kc * 32);
                ldm_x4(A1, qa + kc * 32 + (FA_QL - FA_QH));
                #pragma unroll
                for (int g = 0; g < 4; g++) {
                    uint32_t B[4];
                    ldm_x4(B, ka + kc * 32 + g * 16 * QROWB);
                    mma_bf16(S[2 * g],     A0, B[0], B[2]);
                    mma_bf16(S[2 * g + 1], A0, B[1], B[3]);
                    mma_bf16(S[2 * g],     A1, B[0], B[2]);
                    mma_bf16(S[2 * g + 1], A1, B[1], B[3]);
                    ldm_x4(B, ka + kc * 32 + 17408 + g * 16 * QROWB);
                    mma_bf16(S[2 * g],     A0, B[0], B[2]);
                    mma_bf16(S[2 * g + 1], A0, B[1], B[3]);
                }
            }

            if (k0 + 63 > qrow0) {
                const int r0 = qrow0 + (lane >> 2);
                #pragma unroll
                for (int nt = 0; nt < 8; nt++) {
                    const int c0 = k0 + nt * 8 + (lane & 3) * 2;
                    if (c0     > r0)     S[nt][0] = -1e30f;
                    if (c0 + 1 > r0)     S[nt][1] = -1e30f;
                    if (c0     > r0 + 8) S[nt][2] = -1e30f;
                    if (c0 + 1 > r0 + 8) S[nt][3] = -1e30f;
                }
            }

            #pragma unroll
            for (int r = 0; r < 2; r++) {
                const int i0 = r * 2;
                float rmax = -1e30f;
                #pragma unroll
                for (int nt = 0; nt < 8; nt++)
                    rmax = fmaxf(rmax, fmaxf(S[nt][i0], S[nt][i0 + 1]));
                rmax = fmaxf(rmax, __shfl_xor_sync(0xffffffffu, rmax, 1));
                rmax = fmaxf(rmax, __shfl_xor_sync(0xffffffffu, rmax, 2));
                const float mnew = fmaxf(m2[r], rmax);
                const float corr = ex2f((m2[r] - mnew) * CEXP);
                m2[r] = mnew;
                float psum = 0.f;
                #pragma unroll
                for (int nt = 0; nt < 8; nt++) {
                    float p0 = ex2f((S[nt][i0]     - mnew) * CEXP);
                    float p1 = ex2f((S[nt][i0 + 1] - mnew) * CEXP);
                    S[nt][i0] = p0; S[nt][i0 + 1] = p1;
                    psum += p0 + p1;
                }
                psum += __shfl_xor_sync(0xffffffffu, psum, 1);
                psum += __shfl_xor_sync(0xffffffffu, psum, 2);
                l2[r] = l2[r] * corr + psum;
                #pragma unroll
                for (int nt = 0; nt < 16; nt++) {
                    O[nt][i0]     *= corr;
                    O[nt][i0 + 1] *= corr;
                }
            }

            #pragma unroll
            for (int j = 0; j < 4; j++) {
                uint32_t Ph[4], Pl[4];
                #pragma unroll
                for (int q = 0; q < 2; q++) {
                    const int nt = 2 * j + q;
                    #pragma unroll
                    for (int rr = 0; rr < 2; rr++) {
                        float f0 = S[nt][2 * rr], f1 = S[nt][2 * rr + 1];
                        uint32_t hi = pack_bf16(f0, f1);
                        float g0 = f0 - __bfloat162float(__float2bfloat16_rn(f0));
                        float g1 = f1 - __bfloat162float(__float2bfloat16_rn(f1));
                        uint32_t loo = pack_bf16(g0, g1);
                        Ph[2 * q + rr] = hi;
                        Pl[2 * q + rr] = loo;
                    }
                }
                const int vrow = j * 16 + (lane & 7) + ((lane >> 3) & 1) * 8;
                #pragma unroll
                for (int n = 0; n < 8; n++) {
                    uint32_t va = stb + FA_VH + vrow * QROWB +
                                  (n * 16 + (lane >> 4) * 8) * 2;
                    uint32_t Bv[4];
                    ldm_x4_t(Bv, va);
                    mma_bf16(O[2 * n],     Ph, Bv[0], Bv[1]);
                    mma_bf16(O[2 * n + 1], Ph, Bv[2], Bv[3]);
                    mma_bf16(O[2 * n],     Pl, Bv[0], Bv[1]);
                    mma_bf16(O[2 * n + 1], Pl, Bv[2], Bv[3]);
                    ldm_x4_t(Bv, va + (FA_VL - FA_VH));
                    mma_bf16(O[2 * n],     Ph, Bv[0], Bv[1]);
                    mma_bf16(O[2 * n + 1], Ph, Bv[2], Bv[3]);
                }
            }
        }
        __syncthreads();
    }

    #pragma unroll
    for (int r = 0; r < 2; r++) {
        float inv = 1.0f / l2[r];
        const int row = rowbase + qrow0 + (lane >> 2) + r * 8;
        const size_t off = (size_t)row * DMODEL + h * HD + (lane & 3) * 2;
        #pragma unroll
        for (int nt = 0; nt < 16; nt++) {
            float f0 = O[nt][2 * r] * inv;
            float f1 = O[nt][2 * r + 1] * inv;
            uint32_t hi = pack_bf16(f0, f1);
            float g0 = f0 - __bfloat162float(__float2bfloat16_rn(f0));
            float g1 = f1 - __bfloat162float(__float2bfloat16_rn(f1));
            uint32_t lo = pack_bf16(g0, g1);
            *(uint32_t*)(oh + off + nt * 8) = hi;
            *(uint32_t*)(ol + off + nt * 8) = lo;
        }
    }
}

// ============================================================
// launch
// ============================================================
extern "C" void kernel_launch(void* const* d_in, const int* in_sizes, int n_in,
                              void* d_out, int out_size)
{
    (void)in_sizes; (void)n_in; (void)out_size;
    const float* x      = (const float*)d_in[0];
    const float* w_qkv  = (const float*)d_in[1];
    const float* b_qkv  = (const float*)d_in[2];
    const float* w_o    = (const float*)d_in[3];
    const float* b_o    = (const float*)d_in[4];
    float* out = (float*)d_out;

    float *qkv;
    __nv_bfloat16 *xh, *xl, *wqh, *wql, *woh, *wol, *ah, *al, *qh, *ql;
    cudaGetSymbolAddress((void**)&qkv, g_qkv);
    cudaGetSymbolAddress((void**)&xh,  g_xh);
    cudaGetSymbolAddress((void**)&xl,  g_xl);
    cudaGetSymbolAddress((void**)&wqh, g_wqkvh);
    cudaGetSymbolAddress((void**)&wql, g_wqkvl);
    cudaGetSymbolAddress((void**)&woh, g_woh);
    cudaGetSymbolAddress((void**)&wol, g_wol);
    cudaGetSymbolAddress((void**)&ah,  g_ah);
    cudaGetSymbolAddress((void**)&al,  g_al);
    cudaGetSymbolAddress((void**)&qh,  g_qh);
    cudaGetSymbolAddress((void**)&ql,  g_ql);

    cudaFuncSetAttribute(hmma_gemm_kernel,
                         cudaFuncAttributeMaxDynamicSharedMemorySize, HSMEM);
    cudaFuncSetAttribute(fa_hmma_kernel,
                         cudaFuncAttributeMaxDynamicSharedMemorySize, FA_SMEM);

    // 0) split inputs to bf16 hi/lo
    {
        int n4 = (MROWS * DMODEL) / 4;
        split_bf16_kernel<<<n4 / 256, 256>>>(x, xh, xl, n4);
        int w4 = (QKVDIM * DMODEL) / 4;
        split_bf16_kernel<<<w4 / 256, 256>>>(w_qkv, wqh, wql, w4);
        int o4 = (DMODEL * DMODEL) / 4;
        split_bf16_kernel<<<o4 / 256, 256>>>(w_o, woh, wol, o4);
    }

    // 1) QKV projection (HMMA bf16x3) -> fp32 g_qkv
    hmma_gemm_kernel<<<dim3(QKVDIM / HBN, MROWS / HBM), 512, HSMEM>>>(
        xh, xl, wqh, wql, b_qkv, qkv, MROWS, QKVDIM, DMODEL);

    // 2) RoPE + split to bf16 hi/lo
    rope_split_qk_kernel<<<(MROWS * 64) / 256, 256>>>(qkv, qh, ql);
    split_v_kernel<<<(MROWS * 512) / 256, 256>>>(qkv, qh, ql);

    // 3) HMMA flash attention -> g_ah/g_al (bf16 hi/lo)
    fa_hmma_kernel<<<dim3(SEQLEN / 128, NHEADS, BATCH), 256, FA_SMEM>>>(
        qh, ql, ah, al);

    // 4) O projection (HMMA bf16x3)
    hmma_gemm_kernel<<<dim3(DMODEL / HBN, MROWS / HBM), 512, HSMEM>>>(
        ah, al, woh, wol, b_o, out, MROWS, DMODEL, DMODEL);
}

// round 8
// speedup vs baseline: 1.0017x; 1.0017x over previous
#include <cuda_runtime.h>
#include <cuda_bf16.h>
#include <math.h>
#include <stdint.h>

// ---------------- problem constants ----------------
#define BATCH   2
#define SEQLEN  2048
#define DMODEL  4096
#define NHEADS  32
#define NKV     8
#define HD      128
#define QDIM    (NHEADS * HD)            // 4096
#define KVDIM   (NKV * HD)               // 1024
#define QKVDIM  (QDIM + 2 * KVDIM)       // 6144
#define MROWS   (BATCH * SEQLEN)         // 4096

// ---------------- scratch (device globals: allocation-free) ----------------
__device__ float g_qkv[(size_t)MROWS * QKVDIM];
__device__ __nv_bfloat16 g_xh[(size_t)MROWS * DMODEL];
__device__ __nv_bfloat16 g_xl[(size_t)MROWS * DMODEL];
__device__ __nv_bfloat16 g_wqkvh[(size_t)QKVDIM * DMODEL];
__device__ __nv_bfloat16 g_wqkvl[(size_t)QKVDIM * DMODEL];
__device__ __nv_bfloat16 g_woh[(size_t)DMODEL * DMODEL];
__device__ __nv_bfloat16 g_wol[(size_t)DMODEL * DMODEL];
__device__ __nv_bfloat16 g_ah[(size_t)MROWS * DMODEL];
__device__ __nv_bfloat16 g_al[(size_t)MROWS * DMODEL];
__device__ __nv_bfloat16 g_qh[(size_t)MROWS * QKVDIM];
__device__ __nv_bfloat16 g_ql[(size_t)MROWS * QKVDIM];

// ---------------- helpers ----------------
__device__ __forceinline__ uint32_t smem_to_u32(const void* smem_ptr) {
    uint32_t addr;
    asm("{ .reg .u64 tmp; cvta.to.shared.u64 tmp, %1; cvt.u32.u64 %0, tmp; }"
        : "=r"(addr) : "l"(smem_ptr));
    return addr;
}
__device__ __forceinline__ void cp_async16(uint32_t dst, const void* src) {
    asm volatile("cp.async.cg.shared.global [%0], [%1], 16;\n"
                 :: "r"(dst), "l"(src));
}
__device__ __forceinline__ void cp_commit() {
    asm volatile("cp.async.commit_group;\n" ::: "memory");
}
__device__ __forceinline__ void cp_wait1() {
    asm volatile("cp.async.wait_group 1;\n" ::: "memory");
}
__device__ __forceinline__ void cp_wait2() {
    asm volatile("cp.async.wait_group 2;\n" ::: "memory");
}
__device__ __forceinline__ void ldm_x4(uint32_t* r, uint32_t a) {
    asm volatile("ldmatrix.sync.aligned.m8n8.x4.shared.b16 {%0,%1,%2,%3}, [%4];"
                 : "=r"(r[0]), "=r"(r[1]), "=r"(r[2]), "=r"(r[3]) : "r"(a));
}
__device__ __forceinline__ void ldm_x4_t(uint32_t* r, uint32_t a) {
    asm volatile("ldmatrix.sync.aligned.m8n8.x4.trans.shared.b16 {%0,%1,%2,%3}, [%4];"
                 : "=r"(r[0]), "=r"(r[1]), "=r"(r[2]), "=r"(r[3]) : "r"(a));
}
__device__ __forceinline__ void mma_bf16(float* c, const uint32_t* a,
                                         uint32_t b0, uint32_t b1) {
    asm volatile(
        "mma.sync.aligned.m16n8k16.row.col.f32.bf16.bf16.f32 "
        "{%0,%1,%2,%3}, {%4,%5,%6,%7}, {%8,%9}, {%0,%1,%2,%3};"
        : "+f"(c[0]), "+f"(c[1]), "+f"(c[2]), "+f"(c[3])
        : "r"(a[0]), "r"(a[1]), "r"(a[2]), "r"(a[3]), "r"(b0), "r"(b1));
}
__device__ __forceinline__ float ex2f(float x) {
    float y;
    asm("ex2.approx.f32 %0, %1;" : "=f"(y) : "f"(x));
    return y;
}
__device__ __forceinline__ uint32_t pack_bf16(float f0, float f1) {
    uint16_t b0 = __bfloat16_as_ushort(__float2bfloat16_rn(f0));
    uint16_t b1 = __bfloat16_as_ushort(__float2bfloat16_rn(f1));
    return ((uint32_t)b1 << 16) | (uint32_t)b0;
}

// ============================================================
// HMMA GEMM v2: 512 threads (16 warps, warp tile 64x32),
// CTA tile 128x256, BK=32, 3-stage cp.async pipeline,
// bf16x3 emulation, fp32 accum.
// ============================================================
#define HBM 128
#define HBN 256
#define HBK 32
#define ROWB 80
#define OFF_AH 0
#define OFF_AL 10240
#define OFF_BH 20480
#define OFF_BL 40960
#define STAGE_B 61440
#define HSMEM (3 * STAGE_B)      // 184320 bytes

__device__ __forceinline__ void gemm_load_stage(
    const __nv_bfloat16* __restrict__ Ah, const __nv_bfloat16* __restrict__ Al,
    const __nv_bfloat16* __restrict__ Bh, const __nv_bfloat16* __restrict__ Bl,
    uint32_t sbase, int bm, int bn, int k0, int K, int tid)
{
    // A: 128 rows x 4 chunks x 2 halves = 1024 chunks; 512 threads -> 2 iters
    #pragma unroll
    for (int l = 0; l < 2; l++) {
        int u = tid + l * 512;
        int half = u >> 9;
        int r = (u >> 2) & 127, g = u & 3;
        size_t goff = (size_t)(bm + r) * K + k0 + g * 8;
        cp_async16(sbase + (half ? OFF_AL : OFF_AH) + r * ROWB + g * 16,
                   (half ? Al : Ah) + goff);
    }
    // B: 256 rows x 4 chunks x 2 halves = 2048 chunks; -> 4 iters
    #pragma unroll
    for (int l = 0; l < 4; l++) {
        int u = tid + l * 512;
        int half = u >> 10;
        int r = (u >> 2) & 255, g = u & 3;
        size_t goff = (size_t)(bn + r) * K + k0 + g * 8;
        cp_async16(sbase + (half ? OFF_BL : OFF_BH) + r * ROWB + g * 16,
                   (half ? Bl : Bh) + goff);
    }
}

__global__ __launch_bounds__(512, 1) void hmma_gemm_kernel(
    const __nv_bfloat16* __restrict__ Ah, const __nv_bfloat16* __restrict__ Al,
    const __nv_bfloat16* __restrict__ Bh, const __nv_bfloat16* __restrict__ Bl,
    const float* __restrict__ bias, float* __restrict__ C,
    int M, int N, int K)
{
    extern __shared__ char smem[];
    const uint32_t sb = smem_to_u32(smem);
    const int tid = threadIdx.x;
    const int lane = tid & 31, wid = tid >> 5;
    const int wm = wid & 1;        // 2 warp rows (64 m each)
    const int wn = wid >> 1;       // 8 warp cols (32 n each)
    const int bm = blockIdx.y * HBM;
    const int bn = blockIdx.x * HBN;

    float acc[4][4][4];
    #pragma unroll
    for (int i = 0; i < 4; i++)
        #pragma unroll
        for (int j = 0; j < 4; j++)
            #pragma unroll
            for (int v = 0; v < 4; v++) acc[i][j][v] = 0.f;

    const int NC = K / HBK;

    gemm_load_stage(Ah, Al, Bh, Bl, sb, bm, bn, 0, K, tid);
    cp_commit();
    gemm_load_stage(Ah, Al, Bh, Bl, sb + STAGE_B, bm, bn, HBK, K, tid);
    cp_commit();

    int st = 0;   // stage index of chunk c
    for (int c = 0; c < NC; c++) {
        if (c + 2 < NC) {
            int st2 = st + 2; if (st2 >= 3) st2 -= 3;
            gemm_load_stage(Ah, Al, Bh, Bl, sb + st2 * STAGE_B,
                            bm, bn, (c + 2) * HBK, K, tid);
        }
        cp_commit();
        cp_wait2();
        __syncthreads();

        const uint32_t base = sb + st * STAGE_B;
        #pragma unroll
        for (int ks = 0; ks < 2; ks++) {
            const int kb = ks * 32 + ((lane >> 4) * 16);
            uint32_t a_addr = base + OFF_AH + (wm * 64 + (lane & 15)) * ROWB + kb;
            uint32_t b_addr = base + OFF_BH + (wn * 32 + (lane & 15)) * ROWB + kb;

            uint32_t A0[4][4], A1[4][4], B0[2][4];
            #pragma unroll
            for (int mt = 0; mt < 4; mt++) ldm_x4(A0[mt], a_addr + mt * 16 * ROWB);
            #pragma unroll
            for (int nb = 0; nb < 2; nb++) ldm_x4(B0[nb], b_addr + nb * 16 * ROWB);

            // pass 1: Ah * Bh
            #pragma unroll
            for (int mt = 0; mt < 4; mt++)
                #pragma unroll
                for (int nb = 0; nb < 2; nb++) {
                    mma_bf16(acc[mt][2 * nb],     A0[mt], B0[nb][0], B0[nb][2]);
                    mma_bf16(acc[mt][2 * nb + 1], A0[mt], B0[nb][1], B0[nb][3]);
                }
            // pass 2: Al * Bh
            #pragma unroll
            for (int mt = 0; mt < 4; mt++)
                ldm_x4(A1[mt], a_addr + (OFF_AL - OFF_AH) + mt * 16 * ROWB);
            #pragma unroll
            for (int mt = 0; mt < 4; mt++)
                #pragma unroll
                for (int nb = 0; nb < 2; nb++) {
                    mma_bf16(acc[mt][2 * nb],     A1[mt], B0[nb][0], B0[nb][2]);
                    mma_bf16(acc[mt][2 * nb + 1], A1[mt], B0[nb][1], B0[nb][3]);
                }
            // pass 3: Ah * Bl
            #pragma unroll
            for (int nb = 0; nb < 2; nb++)
                ldm_x4(B0[nb], b_addr + (OFF_BL - OFF_BH) + nb * 16 * ROWB);
            #pragma unroll
            for (int mt = 0; mt < 4; mt++)
                #pragma unroll
                for (int nb = 0; nb < 2; nb++) {
                    mma_bf16(acc[mt][2 * nb],     A0[mt], B0[nb][0], B0[nb][2]);
                    mma_bf16(acc[mt][2 * nb + 1], A0[mt], B0[nb][1], B0[nb][3]);
                }
        }
        __syncthreads();
        if (++st == 3) st = 0;
    }

    // epilogue: fused bias, float2 stores
    #pragma unroll
    for (int mt = 0; mt < 4; mt++) {
        const int row0 = bm + wm * 64 + mt * 16 + (lane >> 2);
        #pragma unroll
        for (int nt = 0; nt < 4; nt++) {
            const int col = bn + wn * 32 + nt * 8 + (lane & 3) * 2;
            const float b0 = bias[col], b1 = bias[col + 1];
            float2 v0 = make_float2(acc[mt][nt][0] + b0, acc[mt][nt][1] + b1);
            float2 v1 = make_float2(acc[mt][nt][2] + b0, acc[mt][nt][3] + b1);
            *(float2*)(C + (size_t)row0 * N + col) = v0;
            *(float2*)(C + (size_t)(row0 + 8) * N + col) = v1;
        }
    }
}

// ============================================================
// fp32 -> bf16 hi/lo split (for x, weights)
// ============================================================
__global__ void split_bf16_kernel(const float* __restrict__ src,
                                  __nv_bfloat16* __restrict__ hi,
                                  __nv_bfloat16* __restrict__ lo, int n4)
{
    int i = blockIdx.x * blockDim.x + threadIdx.x;
    if (i >= n4) return;
    float4 v = ((const float4*)src)[i];
    __nv_bfloat16 h0 = __float2bfloat16(v.x);
    __nv_bfloat16 h1 = __float2bfloat16(v.y);
    __nv_bfloat16 h2 = __float2bfloat16(v.z);
    __nv_bfloat16 h3 = __float2bfloat16(v.w);
    __nv_bfloat16 l0 = __float2bfloat16(v.x - __bfloat162float(h0));
    __nv_bfloat16 l1 = __float2bfloat16(v.y - __bfloat162float(h1));
    __nv_bfloat16 l2 = __float2bfloat16(v.z - __bfloat162float(h2));
    __nv_bfloat16 l3 = __float2bfloat16(v.w - __bfloat162float(h3));
    __nv_bfloat162* hp = (__nv_bfloat162*)hi;
    __nv_bfloat162* lp = (__nv_bfloat162*)lo;
    hp[2 * i]     = __nv_bfloat162(h0, h1);
    hp[2 * i + 1] = __nv_bfloat162(h2, h3);
    lp[2 * i]     = __nv_bfloat162(l0, l1);
    lp[2 * i + 1] = __nv_bfloat162(l2, l3);
}

// ============================================================
// RoPE+split on q/k: one thread per (row, freq-pair) -> 40 heads
// ============================================================
__global__ void rope_split_qk_kernel(const float* __restrict__ qkv,
                                     __nv_bfloat16* __restrict__ oh,
                                     __nv_bfloat16* __restrict__ ol)
{
    int idx = blockIdx.x * blockDim.x + threadIdx.x;   // MROWS*64
    int p = idx & 63;
    int rowi = idx >> 6;
    if (rowi >= MROWS) return;
    int s = rowi & (SEQLEN - 1);

    float inv_freq = powf(10000.0f, -(float)(2 * p) / (float)HD);
    float ang = (float)s * inv_freq;
    float c, sn;
    sincosf(ang, &sn, &c);

    const float* row = qkv + (size_t)rowi * QKVDIM;
    __nv_bfloat16* ohr = oh + (size_t)rowi * QKVDIM;
    __nv_bfloat16* olr = ol + (size_t)rowi * QKVDIM;

    #pragma unroll 4
    for (int hh = 0; hh < NHEADS + NKV; hh++) {
        int col = ((hh < NHEADS) ? hh * HD : QDIM + (hh - NHEADS) * HD) + 2 * p;
        float2 v = *(const float2*)(row + col);
        float r0 = v.x * c - v.y * sn;
        float r1 = v.x * sn + v.y * c;
        __nv_bfloat16 h0 = __float2bfloat16(r0);
        __nv_bfloat16 h1 = __float2bfloat16(r1);
        __nv_bfloat16 l0 = __float2bfloat16(r0 - __bfloat162float(h0));
        __nv_bfloat16 l1 = __float2bfloat16(r1 - __bfloat162float(h1));
        *(__nv_bfloat162*)(ohr + col) = __nv_bfloat162(h0, h1);
        *(__nv_bfloat162*)(olr + col) = __nv_bfloat162(l0, l1);
    }
}

// split-only for V region (cols QDIM+KVDIM .. QKVDIM)
__global__ void split_v_kernel(const float* __restrict__ qkv,
                               __nv_bfloat16* __restrict__ oh,
                               __nv_bfloat16* __restrict__ ol)
{
    int idx = blockIdx.x * blockDim.x + threadIdx.x;   // MROWS*512 pairs
    int c2 = idx & 511;
    int rowi = idx >> 9;
    if (rowi >= MROWS) return;
    size_t off = (size_t)rowi * QKVDIM + QDIM + KVDIM + 2 * c2;
    float2 v = *(const float2*)(g_qkv + off);
    (void)qkv;
    __nv_bfloat16 h0 = __float2bfloat16(v.x);
    __nv_bfloat16 h1 = __float2bfloat16(v.y);
    __nv_bfloat16 l0 = __float2bfloat16(v.x - __bfloat162float(h0));
    __nv_bfloat16 l1 = __float2bfloat16(v.y - __bfloat162float(h1));
    *(__nv_bfloat162*)(oh + off) = __nv_bfloat162(h0, h1);
    *(__nv_bfloat162*)(ol + off) = __nv_bfloat162(l0, l1);
}

// ============================================================
// HMMA flash attention (unchanged from round 5, passing):
// Br=128 (8 warps x 16 rows), Bc=64, bf16x3 for QK^T and PV.
// ============================================================
#define QROWB 272
#define FA_QH  0
#define FA_QL  34816
#define FA_ST0 69632
#define FA_STB 69632
#define FA_KH  0
#define FA_KL  17408
#define FA_VH  34816
#define FA_VL  52224
#define FA_SMEM (69632 + 2 * 69632)

__global__ __launch_bounds__(256) void fa_hmma_kernel(
    const __nv_bfloat16* __restrict__ qh, const __nv_bfloat16* __restrict__ ql,
    __nv_bfloat16* __restrict__ oh, __nv_bfloat16* __restrict__ ol)
{
    extern __shared__ char smem[];
    const uint32_t sb = smem_to_u32(smem);
    const int tid = threadIdx.x;
    const int lane = tid & 31, w = tid >> 5;
    const int b = blockIdx.z, h = blockIdx.y, qb = blockIdx.x;
    const int kvh = h >> 2;
    const int q0 = qb * 128;
    const int rowbase = b * SEQLEN;

    #pragma unroll
    for (int l = 0; l < 16; l++) {
        int u = tid + l * 256;
        int half = u >> 11;
        int r = (u >> 4) & 127;
        int ch = u & 15;
        const __nv_bfloat16* src = (half ? ql : qh) +
            (size_t)(rowbase + q0 + r) * QKVDIM + h * HD + ch * 8;
        cp_async16(sb + (half ? FA_QL : FA_QH) + r * QROWB + ch * 16, src);
    }
    auto load_kv = [&](int t, int s) {
        const int k0 = t * 64;
        const uint32_t stb = sb + FA_ST0 + s * FA_STB;
        #pragma unroll
        for (int l = 0; l < 16; l++) {
            int u = tid + l * 256;
            int sel = u >> 10;
            int r = (u >> 4) & 63;
            int ch = u & 15;
            int gcol = (sel < 2) ? (QDIM + kvh * HD) : (QDIM + KVDIM + kvh * HD);
            const __nv_bfloat16* base = (sel & 1) ? ql : qh;
            const __nv_bfloat16* src = base +
                (size_t)(rowbase + k0 + r) * QKVDIM + gcol + ch * 8;
            cp_async16(stb + sel * 17408 + r * QROWB + ch * 16, src);
        }
    };

    const int tmax = 2 * qb + 2;
    load_kv(0, 0);
    cp_commit();

    const float CEXP = 0.12751742f;
    float m2[2] = {-1e30f, -1e30f};
    float l2[2] = {0.f, 0.f};
    float O[16][4];
    #pragma unroll
    for (int i = 0; i < 16; i++)
        #pragma unroll
        for (int v = 0; v < 4; v++) O[i][v] = 0.f;

    const int qrow0 = q0 + w * 16;

    for (int t = 0; t < tmax; t++) {
        if (t + 1 < tmax) load_kv(t + 1, (t + 1) & 1);
        cp_commit();
        cp_wait1();
        __syncthreads();

        const int k0 = t * 64;
        const uint32_t stb = sb + FA_ST0 + (t & 1) * FA_STB;

        if (k0 <= qrow0 + 15) {
            float S[8][4];
            #pragma unroll
            for (int i = 0; i < 8; i++)
                #pragma unroll
                for (int v = 0; v < 4; v++) S[i][v] = 0.f;

            const uint32_t qa = sb + FA_QH + (w * 16 + (lane & 15)) * QROWB +
                                ((lane >> 4) * 16);
            const uint32_t ka = stb + FA_KH + ((lane & 15)) * QROWB +
                                ((lane >> 4) * 16);
            #pragma unroll
            for (int kc = 0; kc < 8; kc++) {
                uint32_t A0[4], A1[4];
                ldm_x4(A0, qa + kc * 32);
                ldm_x4(A1, qa + kc * 32 + (FA_QL - FA_QH));
                #pragma unroll
                for (int g = 0; g < 4; g++) {
                    uint32_t B[4];
                    ldm_x4(B, ka + kc * 32 + g * 16 * QROWB);
                    mma_bf16(S[2 * g],     A0, B[0], B[2]);
                    mma_bf16(S[2 * g + 1], A0, B[1], B[3]);
                    mma_bf16(S[2 * g],     A1, B[0], B[2]);
                    mma_bf16(S[2 * g + 1], A1, B[1], B[3]);
                    ldm_x4(B, ka + kc * 32 + 17408 + g * 16 * QROWB);
                    mma_bf16(S[2 * g],     A0, B[0], B[2]);
                    mma_bf16(S[2 * g + 1], A0, B[1], B[3]);
                }
            }

            if (k0 + 63 > qrow0) {
                const int r0 = qrow0 + (lane >> 2);
                #pragma unroll
                for (int nt = 0; nt < 8; nt++) {
                    const int c0 = k0 + nt * 8 + (lane & 3) * 2;
                    if (c0     > r0)     S[nt][0] = -1e30f;
                    if (c0 + 1 > r0)     S[nt][1] = -1e30f;
                    if (c0     > r0 + 8) S[nt][2] = -1e30f;
                    if (c0 + 1 > r0 + 8) S[nt][3] = -1e30f;
                }
            }

            #pragma unroll
            for (int r = 0; r < 2; r++) {
                const int i0 = r * 2;
                float rmax = -1e30f;
                #pragma unroll
                for (int nt = 0; nt < 8; nt++)
                    rmax = fmaxf(rmax, fmaxf(S[nt][i0], S[nt][i0 + 1]));
                rmax = fmaxf(rmax, __shfl_xor_sync(0xffffffffu, rmax, 1));
                rmax = fmaxf(rmax, __shfl_xor_sync(0xffffffffu, rmax, 2));
                const float mnew = fmaxf(m2[r], rmax);
                const float corr = ex2f((m2[r] - mnew) * CEXP);
                m2[r] = mnew;
                float psum = 0.f;
                #pragma unroll
                for (int nt = 0; nt < 8; nt++) {
                    float p0 = ex2f((S[nt][i0]     - mnew) * CEXP);
                    float p1 = ex2f((S[nt][i0 + 1] - mnew) * CEXP);
                    S[nt][i0] = p0; S[nt][i0 + 1] = p1;
                    psum += p0 + p1;
                }
                psum += __shfl_xor_sync(0xffffffffu, psum, 1);
                psum += __shfl_xor_sync(0xffffffffu, psum, 2);
                l2[r] = l2[r] * corr + psum;
                #pragma unroll
                for (int nt = 0; nt < 16; nt++) {
                    O[nt][i0]     *= corr;
                    O[nt][i0 + 1] *= corr;
                }
            }

            #pragma unroll
            for (int j = 0; j < 4; j++) {
                uint32_t Ph[4], Pl[4];
                #pragma unroll
                for (int q = 0; q < 2; q++) {
                    const int nt = 2 * j + q;
                    #pragma unroll
                    for (int rr = 0; rr < 2; rr++) {
                        float f0 = S[nt][2 * rr], f1 = S[nt][2 * rr + 1];
                        uint32_t hi = pack_bf16(f0, f1);
                        float g0 = f0 - __bfloat162float(__float2bfloat16_rn(f0));
                        float g1 = f1 - __bfloat162float(__float2bfloat16_rn(f1));
                        uint32_t loo = pack_bf16(g0, g1);
                        Ph[2 * q + rr] = hi;
                        Pl[2 * q + rr] = loo;
                    }
                }
                const int vrow = j * 16 + (lane & 7) + ((lane >> 3) & 1) * 8;
                #pragma unroll
                for (int n = 0; n < 8; n++) {
                    uint32_t va = stb + FA_VH + vrow * QROWB +
                                  (n * 16 + (lane >> 4) * 8) * 2;
                    uint32_t Bv[4];
                    ldm_x4_t(Bv, va);
                    mma_bf16(O[2 * n],     Ph, Bv[0], Bv[1]);
                    mma_bf16(O[2 * n + 1], Ph, Bv[2], Bv[3]);
                    mma_bf16(O[2 * n],     Pl, Bv[0], Bv[1]);
                    mma_bf16(O[2 * n + 1], Pl, Bv[2], Bv[3]);
                    ldm_x4_t(Bv, va + (FA_VL - FA_VH));
                    mma_bf16(O[2 * n],     Ph, Bv[0], Bv[1]);
                    mma_bf16(O[2 * n + 1], Ph, Bv[2], Bv[3]);
                }
            }
        }
        __syncthreads();
    }

    #pragma unroll
    for (int r = 0; r < 2; r++) {
        float inv = 1.0f / l2[r];
        const int row = rowbase + qrow0 + (lane >> 2) + r * 8;
        const size_t off = (size_t)row * DMODEL + h * HD + (lane & 3) * 2;
        #pragma unroll
        for (int nt = 0; nt < 16; nt++) {
            float f0 = O[nt][2 * r] * inv;
            float f1 = O[nt][2 * r + 1] * inv;
            uint32_t hi = pack_bf16(f0, f1);
            float g0 = f0 - __bfloat162float(__float2bfloat16_rn(f0));
            float g1 = f1 - __bfloat162float(__float2bfloat16_rn(f1));
            uint32_t lo = pack_bf16(g0, g1);
            *(uint32_t*)(oh + off + nt * 8) = hi;
            *(uint32_t*)(ol + off + nt * 8) = lo;
        }
    }
}

// ============================================================
// launch
// ============================================================
extern "C" void kernel_launch(void* const* d_in, const int* in_sizes, int n_in,
                              void* d_out, int out_size)
{
    (void)in_sizes; (void)n_in; (void)out_size;
    const float* x      = (const float*)d_in[0];
    const float* w_qkv  = (const float*)d_in[1];
    const float* b_qkv  = (const float*)d_in[2];
    const float* w_o    = (const float*)d_in[3];
    const float* b_o    = (const float*)d_in[4];
    float* out = (float*)d_out;

    float *qkv;
    __nv_bfloat16 *xh, *xl, *wqh, *wql, *woh, *wol, *ah, *al, *qh, *ql;
    cudaGetSymbolAddress((void**)&qkv, g_qkv);
    cudaGetSymbolAddress((void**)&xh,  g_xh);
    cudaGetSymbolAddress((void**)&xl,  g_xl);
    cudaGetSymbolAddress((void**)&wqh, g_wqkvh);
    cudaGetSymbolAddress((void**)&wql, g_wqkvl);
    cudaGetSymbolAddress((void**)&woh, g_woh);
    cudaGetSymbolAddress((void**)&wol, g_wol);
    cudaGetSymbolAddress((void**)&ah,  g_ah);
    cudaGetSymbolAddress((void**)&al,  g_al);
    cudaGetSymbolAddress((void**)&qh,  g_qh);
    cudaGetSymbolAddress((void**)&ql,  g_ql);

    cudaFuncSetAttribute(hmma_gemm_kernel,
                         cudaFuncAttributeMaxDynamicSharedMemorySize, HSMEM);
    cudaFuncSetAttribute(fa_hmma_kernel,
                         cudaFuncAttributeMaxDynamicSharedMemorySize, FA_SMEM);

    // 0) split inputs to bf16 hi/lo
    {
        int n4 = (MROWS * DMODEL) / 4;
        split_bf16_kernel<<<n4 / 256, 256>>>(x, xh, xl, n4);
        int w4 = (QKVDIM * DMODEL) / 4;
        split_bf16_kernel<<<w4 / 256, 256>>>(w_qkv, wqh, wql, w4);
        int o4 = (DMODEL * DMODEL) / 4;
        split_bf16_kernel<<<o4 / 256, 256>>>(w_o, woh, wol, o4);
    }

    // 1) QKV projection (HMMA bf16x3) -> fp32 g_qkv
    hmma_gemm_kernel<<<dim3(QKVDIM / HBN, MROWS / HBM), 512, HSMEM>>>(
        xh, xl, wqh, wql, b_qkv, qkv, MROWS, QKVDIM, DMODEL);

    // 2) RoPE + split to bf16 hi/lo
    rope_split_qk_kernel<<<(MROWS * 64) / 256, 256>>>(qkv, qh, ql);
    split_v_kernel<<<(MROWS * 512) / 256, 256>>>(qkv, qh, ql);

    // 3) HMMA flash attention -> g_ah/g_al (bf16 hi/lo)
    fa_hmma_kernel<<<dim3(SEQLEN / 128, NHEADS, BATCH), 256, FA_SMEM>>>(
        qh, ql, ah, al);

    // 4) O projection (HMMA bf16x3)
    hmma_gemm_kernel<<<dim3(DMODEL / HBN, MROWS / HBM), 512, HSMEM>>>(
        ah, al, woh, wol, b_o, out, MROWS, DMODEL, DMODEL);
}

// round 9
// speedup vs baseline: 1.4581x; 1.4556x over previous
#include <cuda_runtime.h>
#include <cuda_fp16.h>
#include <math.h>
#include <stdint.h>

// ---------------- problem constants ----------------
#define BATCH   2
#define SEQLEN  2048
#define DMODEL  4096
#define NHEADS  32
#define NKV     8
#define HD      128
#define QDIM    (NHEADS * HD)            // 4096
#define KVDIM   (NKV * HD)               // 1024
#define QKVDIM  (QDIM + 2 * KVDIM)       // 6144
#define MROWS   (BATCH * SEQLEN)         // 4096

// ---------------- scratch (device globals: allocation-free) ----------------
__device__ float g_qkv[(size_t)MROWS * QKVDIM];
__device__ __half g_xh[(size_t)MROWS * DMODEL];
__device__ __half g_xl[(size_t)MROWS * DMODEL];
__device__ __half g_wqkvh[(size_t)QKVDIM * DMODEL];
__device__ __half g_woh[(size_t)DMODEL * DMODEL];
__device__ __half g_ah[(size_t)MROWS * DMODEL];
__device__ __half g_al[(size_t)MROWS * DMODEL];
__device__ __half g_qh[(size_t)MROWS * QKVDIM];   // rope'd qkv hi
__device__ __half g_ql[(size_t)MROWS * QKVDIM];   // rope'd q lo (q region only)

// ---------------- helpers ----------------
__device__ __forceinline__ uint32_t smem_to_u32(const void* smem_ptr) {
    uint32_t addr;
    asm("{ .reg .u64 tmp; cvta.to.shared.u64 tmp, %1; cvt.u32.u64 %0, tmp; }"
        : "=r"(addr) : "l"(smem_ptr));
    return addr;
}
__device__ __forceinline__ void cp_async16(uint32_t dst, const void* src) {
    asm volatile("cp.async.cg.shared.global [%0], [%1], 16;\n"
                 :: "r"(dst), "l"(src));
}
__device__ __forceinline__ void cp_commit() {
    asm volatile("cp.async.commit_group;\n" ::: "memory");
}
__device__ __forceinline__ void cp_wait1() {
    asm volatile("cp.async.wait_group 1;\n" ::: "memory");
}
__device__ __forceinline__ void cp_wait2() {
    asm volatile("cp.async.wait_group 2;\n" ::: "memory");
}
__device__ __forceinline__ void ldm_x4(uint32_t* r, uint32_t a) {
    asm volatile("ldmatrix.sync.aligned.m8n8.x4.shared.b16 {%0,%1,%2,%3}, [%4];"
                 : "=r"(r[0]), "=r"(r[1]), "=r"(r[2]), "=r"(r[3]) : "r"(a));
}
__device__ __forceinline__ void ldm_x4_t(uint32_t* r, uint32_t a) {
    asm volatile("ldmatrix.sync.aligned.m8n8.x4.trans.shared.b16 {%0,%1,%2,%3}, [%4];"
                 : "=r"(r[0]), "=r"(r[1]), "=r"(r[2]), "=r"(r[3]) : "r"(a));
}
__device__ __forceinline__ void mma_fp16(float* c, const uint32_t* a,
                                         uint32_t b0, uint32_t b1) {
    asm volatile(
        "mma.sync.aligned.m16n8k16.row.col.f32.f16.f16.f32 "
        "{%0,%1,%2,%3}, {%4,%5,%6,%7}, {%8,%9}, {%0,%1,%2,%3};"
        : "+f"(c[0]), "+f"(c[1]), "+f"(c[2]), "+f"(c[3])
        : "r"(a[0]), "r"(a[1]), "r"(a[2]), "r"(a[3]), "r"(b0), "r"(b1));
}
__device__ __forceinline__ float ex2f(float x) {
    float y;
    asm("ex2.approx.f32 %0, %1;" : "=f"(y) : "f"(x));
    return y;
}
__device__ __forceinline__ uint32_t pack_fp16(float f0, float f1) {
    uint16_t b0 = __half_as_ushort(__float2half_rn(f0));
    uint16_t b1 = __half_as_ushort(__float2half_rn(f1));
    return ((uint32_t)b1 << 16) | (uint32_t)b0;
}

// ============================================================
// HMMA GEMM v3 (fp16 2-pass): C = (Ah+Al)[M,K] @ Bh[N,K]^T + bias
// 512 threads (16 warps, warp tile 64x32), CTA tile 128x256,
// BK=32, 3-stage cp.async pipeline, fp32 accum.
// Exact in A; error = fp16 quantization of B only.
// ============================================================
#define HBM 128
#define HBN 256
#define HBK 32
#define ROWB 80
#define OFF_AH 0
#define OFF_AL 10240
#define OFF_BH 20480
#define STAGE_B 40960
#define HSMEM (3 * STAGE_B)      // 122880 bytes

__device__ __forceinline__ void gemm_load_stage(
    const __half* __restrict__ Ah, const __half* __restrict__ Al,
    const __half* __restrict__ Bh,
    uint32_t sbase, int bm, int bn, int k0, int K, int tid)
{
    // A hi+lo: 128 rows x 4 chunks x 2 halves = 1024 chunks; 512 thr -> 2 iters
    #pragma unroll
    for (int l = 0; l < 2; l++) {
        int u = tid + l * 512;
        int half_ = u >> 9;
        int r = (u >> 2) & 127, g = u & 3;
        size_t goff = (size_t)(bm + r) * K + k0 + g * 8;
        cp_async16(sbase + (half_ ? OFF_AL : OFF_AH) + r * ROWB + g * 16,
                   (half_ ? Al : Ah) + goff);
    }
    // B hi: 256 rows x 4 chunks = 1024 chunks -> 2 iters
    #pragma unroll
    for (int l = 0; l < 2; l++) {
        int u = tid + l * 512;
        int r = (u >> 2) & 255, g = u & 3;
        size_t goff = (size_t)(bn + r) * K + k0 + g * 8;
        cp_async16(sbase + OFF_BH + r * ROWB + g * 16, Bh + goff);
    }
}

__global__ __launch_bounds__(512, 1) void hmma_gemm_kernel(
    const __half* __restrict__ Ah, const __half* __restrict__ Al,
    const __half* __restrict__ Bh,
    const float* __restrict__ bias, float* __restrict__ C,
    int M, int N, int K)
{
    extern __shared__ char smem[];
    const uint32_t sb = smem_to_u32(smem);
    const int tid = threadIdx.x;
    const int lane = tid & 31, wid = tid >> 5;
    const int wm = wid & 1;        // 2 warp rows (64 m each)
    const int wn = wid >> 1;       // 8 warp cols (32 n each)
    const int bm = blockIdx.y * HBM;
    const int bn = blockIdx.x * HBN;

    float acc[4][4][4];
    #pragma unroll
    for (int i = 0; i < 4; i++)
        #pragma unroll
        for (int j = 0; j < 4; j++)
            #pragma unroll
            for (int v = 0; v < 4; v++) acc[i][j][v] = 0.f;

    const int NC = K / HBK;

    gemm_load_stage(Ah, Al, Bh, sb, bm, bn, 0, K, tid);
    cp_commit();
    gemm_load_stage(Ah, Al, Bh, sb + STAGE_B, bm, bn, HBK, K, tid);
    cp_commit();

    int st = 0;
    for (int c = 0; c < NC; c++) {
        if (c + 2 < NC) {
            int st2 = st + 2; if (st2 >= 3) st2 -= 3;
            gemm_load_stage(Ah, Al, Bh, sb + st2 * STAGE_B,
                            bm, bn, (c + 2) * HBK, K, tid);
        }
        cp_commit();
        cp_wait2();
        __syncthreads();

        const uint32_t base = sb + st * STAGE_B;
        #pragma unroll
        for (int ks = 0; ks < 2; ks++) {
            const int kb = ks * 32 + ((lane >> 4) * 16);
            uint32_t a_addr = base + OFF_AH + (wm * 64 + (lane & 15)) * ROWB + kb;
            uint32_t b_addr = base + OFF_BH + (wn * 32 + (lane & 15)) * ROWB + kb;

            uint32_t A0[4][4], A1[4][4], B0[2][4];
            #pragma unroll
            for (int mt = 0; mt < 4; mt++) ldm_x4(A0[mt], a_addr + mt * 16 * ROWB);
            #pragma unroll
            for (int nb = 0; nb < 2; nb++) ldm_x4(B0[nb], b_addr + nb * 16 * ROWB);

            // pass 1: Ah * Bh
            #pragma unroll
            for (int mt = 0; mt < 4; mt++)
                #pragma unroll
                for (int nb = 0; nb < 2; nb++) {
                    mma_fp16(acc[mt][2 * nb],     A0[mt], B0[nb][0], B0[nb][2]);
                    mma_fp16(acc[mt][2 * nb + 1], A0[mt], B0[nb][1], B0[nb][3]);
                }
            // pass 2: Al * Bh
            #pragma unroll
            for (int mt = 0; mt < 4; mt++)
                ldm_x4(A1[mt], a_addr + (OFF_AL - OFF_AH) + mt * 16 * ROWB);
            #pragma unroll
            for (int mt = 0; mt < 4; mt++)
                #pragma unroll
                for (int nb = 0; nb < 2; nb++) {
                    mma_fp16(acc[mt][2 * nb],     A1[mt], B0[nb][0], B0[nb][2]);
                    mma_fp16(acc[mt][2 * nb + 1], A1[mt], B0[nb][1], B0[nb][3]);
                }
        }
        __syncthreads();
        if (++st == 3) st = 0;
    }

    #pragma unroll
    for (int mt = 0; mt < 4; mt++) {
        const int row0 = bm + wm * 64 + mt * 16 + (lane >> 2);
        #pragma unroll
        for (int nt = 0; nt < 4; nt++) {
            const int col = bn + wn * 32 + nt * 8 + (lane & 3) * 2;
            const float b0 = bias[col], b1 = bias[col + 1];
            float2 v0 = make_float2(acc[mt][nt][0] + b0, acc[mt][nt][1] + b1);
            float2 v1 = make_float2(acc[mt][nt][2] + b0, acc[mt][nt][3] + b1);
            *(float2*)(C + (size_t)row0 * N + col) = v0;
            *(float2*)(C + (size_t)(row0 + 8) * N + col) = v1;
        }
    }
}

// ============================================================
// fp32 -> fp16 hi/lo split (activations)
// ============================================================
__global__ void split_fp16_kernel(const float* __restrict__ src,
                                  __half* __restrict__ hi,
                                  __half* __restrict__ lo, int n4)
{
    int i = blockIdx.x * blockDim.x + threadIdx.x;
    if (i >= n4) return;
    float4 v = ((const float4*)src)[i];
    __half h0 = __float2half_rn(v.x);
    __half h1 = __float2half_rn(v.y);
    __half h2 = __float2half_rn(v.z);
    __half h3 = __float2half_rn(v.w);
    __half l0 = __float2half_rn(v.x - __half2float(h0));
    __half l1 = __float2half_rn(v.y - __half2float(h1));
    __half l2 = __float2half_rn(v.z - __half2float(h2));
    __half l3 = __float2half_rn(v.w - __half2float(h3));
    __half2* hp = (__half2*)hi;
    __half2* lp = (__half2*)lo;
    hp[2 * i]     = __halves2half2(h0, h1);
    hp[2 * i + 1] = __halves2half2(h2, h3);
    lp[2 * i]     = __halves2half2(l0, l1);
    lp[2 * i + 1] = __halves2half2(l2, l3);
}

// fp32 -> fp16 (weights, hi only)
__global__ void convert_fp16_kernel(const float* __restrict__ src,
                                    __half* __restrict__ hi, int n4)
{
    int i = blockIdx.x * blockDim.x + threadIdx.x;
    if (i >= n4) return;
    float4 v = ((const float4*)src)[i];
    __half2* hp = (__half2*)hi;
    hp[2 * i]     = __halves2half2(__float2half_rn(v.x), __float2half_rn(v.y));
    hp[2 * i + 1] = __halves2half2(__float2half_rn(v.z), __float2half_rn(v.w));
}

// ============================================================
// RoPE+split on q/k: one thread per (row, freq-pair).
// q heads: hi+lo.  k heads: hi only (K-lo never used).
// ============================================================
__global__ void rope_split_qk_kernel(const float* __restrict__ qkv,
                                     __half* __restrict__ oh,
                                     __half* __restrict__ ol)
{
    int idx = blockIdx.x * blockDim.x + threadIdx.x;   // MROWS*64
    int p = idx & 63;
    int rowi = idx >> 6;
    if (rowi >= MROWS) return;
    int s = rowi & (SEQLEN - 1);

    float inv_freq = powf(10000.0f, -(float)(2 * p) / (float)HD);
    float ang = (float)s * inv_freq;
    float c, sn;
    sincosf(ang, &sn, &c);

    const float* row = qkv + (size_t)rowi * QKVDIM;
    __half* ohr = oh + (size_t)rowi * QKVDIM;
    __half* olr = ol + (size_t)rowi * QKVDIM;

    #pragma unroll 4
    for (int hh = 0; hh < NHEADS + NKV; hh++) {
        int col = ((hh < NHEADS) ? hh * HD : QDIM + (hh - NHEADS) * HD) + 2 * p;
        float2 v = *(const float2*)(row + col);
        float r0 = v.x * c - v.y * sn;
        float r1 = v.x * sn + v.y * c;
        __half h0 = __float2half_rn(r0);
        __half h1 = __float2half_rn(r1);
        *(__half2*)(ohr + col) = __halves2half2(h0, h1);
        if (hh < NHEADS) {
            __half l0 = __float2half_rn(r0 - __half2float(h0));
            __half l1 = __float2half_rn(r1 - __half2float(h1));
            *(__half2*)(olr + col) = __halves2half2(l0, l1);
        }
    }
}

// split-only for V region (hi only)
__global__ void split_v_kernel(__half* __restrict__ oh)
{
    int idx = blockIdx.x * blockDim.x + threadIdx.x;   // MROWS*512 pairs
    int c2 = idx & 511;
    int rowi = idx >> 9;
    if (rowi >= MROWS) return;
    size_t off = (size_t)rowi * QKVDIM + QDIM + KVDIM + 2 * c2;
    float2 v = *(const float2*)(g_qkv + off);
    *(__half2*)(oh + off) =
        __halves2half2(__float2half_rn(v.x), __float2half_rn(v.y));
}

// ============================================================
// HMMA flash attention (fp16 2-pass):
// Br=128 (8 warps x 16 rows), Bc=64.
// scores = (Qh+Ql)·Kh ; O += (Ph+Pl)·Vh. Output -> fp16 hi/lo.
// ============================================================
#define QROWB 272
#define FA_QH  0
#define FA_QL  34816
#define FA_ST0 69632
#define FA_STB 34816          // Kh + Vh per stage
#define FA_KH  0
#define FA_VH  17408
#define FA_SMEM (69632 + 2 * 34816)   // 139264

__global__ __launch_bounds__(256) void fa_hmma_kernel(
    const __half* __restrict__ qh, const __half* __restrict__ ql,
    __half* __restrict__ oh, __half* __restrict__ ol)
{
    extern __shared__ char smem[];
    const uint32_t sb = smem_to_u32(smem);
    const int tid = threadIdx.x;
    const int lane = tid & 31, w = tid >> 5;
    const int b = blockIdx.z, h = blockIdx.y, qb = blockIdx.x;
    const int kvh = h >> 2;
    const int q0 = qb * 128;
    const int rowbase = b * SEQLEN;

    // Q tile hi+lo: 4096 chunks -> 16 iters
    #pragma unroll
    for (int l = 0; l < 16; l++) {
        int u = tid + l * 256;
        int half_ = u >> 11;
        int r = (u >> 4) & 127;
        int ch = u & 15;
        const __half* src = (half_ ? ql : qh) +
            (size_t)(rowbase + q0 + r) * QKVDIM + h * HD + ch * 8;
        cp_async16(sb + (half_ ? FA_QL : FA_QH) + r * QROWB + ch * 16, src);
    }
    // KV stage: Kh + Vh = 2048 chunks -> 8 iters
    auto load_kv = [&](int t, int s) {
        const int k0 = t * 64;
        const uint32_t stb = sb + FA_ST0 + s * FA_STB;
        #pragma unroll
        for (int l = 0; l < 8; l++) {
            int u = tid + l * 256;
            int sel = u >> 10;            // 0 Kh, 1 Vh
            int r = (u >> 4) & 63;
            int ch = u & 15;
            int gcol = sel ? (QDIM + KVDIM + kvh * HD) : (QDIM + kvh * HD);
            const __half* src = qh +
                (size_t)(rowbase + k0 + r) * QKVDIM + gcol + ch * 8;
            cp_async16(stb + sel * 17408 + r * QROWB + ch * 16, src);
        }
    };

    const int tmax = 2 * qb + 2;
    load_kv(0, 0);
    cp_commit();

    const float CEXP = 0.12751742f;       // (1/sqrt(128)) * log2(e)
    float m2[2] = {-1e30f, -1e30f};
    float l2[2] = {0.f, 0.f};
    float O[16][4];
    #pragma unroll
    for (int i = 0; i < 16; i++)
        #pragma unroll
        for (int v = 0; v < 4; v++) O[i][v] = 0.f;

    const int qrow0 = q0 + w * 16;

    for (int t = 0; t < tmax; t++) {
        if (t + 1 < tmax) load_kv(t + 1, (t + 1) & 1);
        cp_commit();
        cp_wait1();
        __syncthreads();

        const int k0 = t * 64;
        const uint32_t stb = sb + FA_ST0 + (t & 1) * FA_STB;

        if (k0 <= qrow0 + 15) {
            // ---------- scores S = (Qh+Ql) Kh^T ----------
            float S[8][4];
            #pragma unroll
            for (int i = 0; i < 8; i++)
                #pragma unroll
                for (int v = 0; v < 4; v++) S[i][v] = 0.f;

            const uint32_t qa = sb + FA_QH + (w * 16 + (lane & 15)) * QROWB +
                                ((lane >> 4) * 16);
            const uint32_t ka = stb + FA_KH + ((lane & 15)) * QROWB +
                                ((lane >> 4) * 16);
            #pragma unroll
            for (int kc = 0; kc < 8; kc++) {
                uint32_t A0[4], A1[4];
                ldm_x4(A0, qa + kc * 32);
                ldm_x4(A1, qa + kc * 32 + (FA_QL - FA_QH));
                #pragma unroll
                for (int g = 0; g < 4; g++) {
                    uint32_t B[4];
                    ldm_x4(B, ka + kc * 32 + g * 16 * QROWB);
                    mma_fp16(S[2 * g],     A0, B[0], B[2]);
                    mma_fp16(S[2 * g + 1], A0, B[1], B[3]);
                    mma_fp16(S[2 * g],     A1, B[0], B[2]);
                    mma_fp16(S[2 * g + 1], A1, B[1], B[3]);
                }
            }

            // ---------- causal mask ----------
            if (k0 + 63 > qrow0) {
                const int r0 = qrow0 + (lane >> 2);
                #pragma unroll
                for (int nt = 0; nt < 8; nt++) {
                    const int c0 = k0 + nt * 8 + (lane & 3) * 2;
                    if (c0     > r0)     S[nt][0] = -1e30f;
                    if (c0 + 1 > r0)     S[nt][1] = -1e30f;
                    if (c0     > r0 + 8) S[nt][2] = -1e30f;
                    if (c0 + 1 > r0 + 8) S[nt][3] = -1e30f;
                }
            }

            // ---------- online softmax ----------
            #pragma unroll
            for (int r = 0; r < 2; r++) {
                const int i0 = r * 2;
                float rmax = -1e30f;
                #pragma unroll
                for (int nt = 0; nt < 8; nt++)
                    rmax = fmaxf(rmax, fmaxf(S[nt][i0], S[nt][i0 + 1]));
                rmax = fmaxf(rmax, __shfl_xor_sync(0xffffffffu, rmax, 1));
                rmax = fmaxf(rmax, __shfl_xor_sync(0xffffffffu, rmax, 2));
                const float mnew = fmaxf(m2[r], rmax);
                const float corr = ex2f((m2[r] - mnew) * CEXP);
                m2[r] = mnew;
                float psum = 0.f;
                #pragma unroll
                for (int nt = 0; nt < 8; nt++) {
                    float p0 = ex2f((S[nt][i0]     - mnew) * CEXP);
                    float p1 = ex2f((S[nt][i0 + 1] - mnew) * CEXP);
                    S[nt][i0] = p0; S[nt][i0 + 1] = p1;
                    psum += p0 + p1;
                }
                psum += __shfl_xor_sync(0xffffffffu, psum, 1);
                psum += __shfl_xor_sync(0xffffffffu, psum, 2);
                l2[r] = l2[r] * corr + psum;
                #pragma unroll
                for (int nt = 0; nt < 16; nt++) {
                    O[nt][i0]     *= corr;
                    O[nt][i0 + 1] *= corr;
                }
            }

            // ---------- PV: O += (Ph+Pl) Vh ----------
            #pragma unroll
            for (int j = 0; j < 4; j++) {
                uint32_t Ph[4], Pl[4];
                #pragma unroll
                for (int q = 0; q < 2; q++) {
                    const int nt = 2 * j + q;
                    #pragma unroll
                    for (int rr = 0; rr < 2; rr++) {
                        float f0 = S[nt][2 * rr], f1 = S[nt][2 * rr + 1];
                        uint32_t hi = pack_fp16(f0, f1);
                        float g0 = f0 - __half2float(__float2half_rn(f0));
                        float g1 = f1 - __half2float(__float2half_rn(f1));
                        Ph[2 * q + rr] = hi;
                        Pl[2 * q + rr] = pack_fp16(g0, g1);
                    }
                }
                const int vrow = j * 16 + (lane & 7) + ((lane >> 3) & 1) * 8;
                #pragma unroll
                for (int n = 0; n < 8; n++) {
                    uint32_t va = stb + FA_VH + vrow * QROWB +
                                  (n * 16 + (lane >> 4) * 8) * 2;
                    uint32_t Bv[4];
                    ldm_x4_t(Bv, va);
                    mma_fp16(O[2 * n],     Ph, Bv[0], Bv[1]);
                    mma_fp16(O[2 * n + 1], Ph, Bv[2], Bv[3]);
                    mma_fp16(O[2 * n],     Pl, Bv[0], Bv[1]);
                    mma_fp16(O[2 * n + 1], Pl, Bv[2], Bv[3]);
                }
            }
        }
        __syncthreads();
    }

    // ---------- epilogue: normalize, split to fp16 hi/lo ----------
    #pragma unroll
    for (int r = 0; r < 2; r++) {
        float inv = 1.0f / l2[r];
        const int row = rowbase + qrow0 + (lane >> 2) + r * 8;
        const size_t off = (size_t)row * DMODEL + h * HD + (lane & 3) * 2;
        #pragma unroll
        for (int nt = 0; nt < 16; nt++) {
            float f0 = O[nt][2 * r] * inv;
            float f1 = O[nt][2 * r + 1] * inv;
            uint32_t hi = pack_fp16(f0, f1);
            float g0 = f0 - __half2float(__float2half_rn(f0));
            float g1 = f1 - __half2float(__float2half_rn(f1));
            uint32_t lo = pack_fp16(g0, g1);
            *(uint32_t*)(oh + off + nt * 8) = hi;
            *(uint32_t*)(ol + off + nt * 8) = lo;
        }
    }
}

// ============================================================
// launch
// ============================================================
extern "C" void kernel_launch(void* const* d_in, const int* in_sizes, int n_in,
                              void* d_out, int out_size)
{
    (void)in_sizes; (void)n_in; (void)out_size;
    const float* x      = (const float*)d_in[0];
    const float* w_qkv  = (const float*)d_in[1];
    const float* b_qkv  = (const float*)d_in[2];
    const float* w_o    = (const float*)d_in[3];
    const float* b_o    = (const float*)d_in[4];
    float* out = (float*)d_out;

    float *qkv;
    __half *xh, *xl, *wqh, *woh, *ah, *al, *qh, *ql;
    cudaGetSymbolAddress((void**)&qkv, g_qkv);
    cudaGetSymbolAddress((void**)&xh,  g_xh);
    cudaGetSymbolAddress((void**)&xl,  g_xl);
    cudaGetSymbolAddress((void**)&wqh, g_wqkvh);
    cudaGetSymbolAddress((void**)&woh, g_woh);
    cudaGetSymbolAddress((void**)&ah,  g_ah);
    cudaGetSymbolAddress((void**)&al,  g_al);
    cudaGetSymbolAddress((void**)&qh,  g_qh);
    cudaGetSymbolAddress((void**)&ql,  g_ql);

    cudaFuncSetAttribute(hmma_gemm_kernel,
                         cudaFuncAttributeMaxDynamicSharedMemorySize, HSMEM);
    cudaFuncSetAttribute(fa_hmma_kernel,
                         cudaFuncAttributeMaxDynamicSharedMemorySize, FA_SMEM);

    // 0) split x (hi/lo); convert weights (hi only)
    {
        int n4 = (MROWS * DMODEL) / 4;
        split_fp16_kernel<<<n4 / 256, 256>>>(x, xh, xl, n4);
        int w4 = (QKVDIM * DMODEL) / 4;
        convert_fp16_kernel<<<w4 / 256, 256>>>(w_qkv, wqh, w4);
        int o4 = (DMODEL * DMODEL) / 4;
        convert_fp16_kernel<<<o4 / 256, 256>>>(w_o, woh, o4);
    }

    // 1) QKV projection (fp16 2-pass) -> fp32 g_qkv
    hmma_gemm_kernel<<<dim3(QKVDIM / HBN, MROWS / HBM), 512, HSMEM>>>(
        xh, xl, wqh, b_qkv, qkv, MROWS, QKVDIM, DMODEL);

    // 2) RoPE + split (q: hi/lo, k: hi), V convert (hi)
    rope_split_qk_kernel<<<(MROWS * 64) / 256, 256>>>(qkv, qh, ql);
    split_v_kernel<<<(MROWS * 512) / 256, 256>>>(qh);

    // 3) fp16 flash attention -> g_ah/g_al (fp16 hi/lo)
    fa_hmma_kernel<<<dim3(SEQLEN / 128, NHEADS, BATCH), 256, FA_SMEM>>>(
        qh, ql, ah, al);

    // 4) O projection (fp16 2-pass)
    hmma_gemm_kernel<<<dim3(DMODEL / HBN, MROWS / HBM), 512, HSMEM>>>(
        ah, al, woh, b_o, out, MROWS, DMODEL, DMODEL);
}

// round 10
// speedup vs baseline: 1.5061x; 1.0329x over previous
#include <cuda_runtime.h>
#include <cuda_fp16.h>
#include <math.h>
#include <stdint.h>

// ---------------- problem constants ----------------
#define BATCH   2
#define SEQLEN  2048
#define DMODEL  4096
#define NHEADS  32
#define NKV     8
#define HD      128
#define QDIM    (NHEADS * HD)            // 4096
#define KVDIM   (NKV * HD)               // 1024
#define QKVDIM  (QDIM + 2 * KVDIM)       // 6144
#define MROWS   (BATCH * SEQLEN)         // 4096

// ---------------- scratch (device globals: allocation-free) ----------------
__device__ float g_qkv[(size_t)MROWS * QKVDIM];
__device__ __half g_xh[(size_t)MROWS * DMODEL];
__device__ __half g_xl[(size_t)MROWS * DMODEL];
__device__ __half g_wqkvh[(size_t)QKVDIM * DMODEL];
__device__ __half g_woh[(size_t)DMODEL * DMODEL];
__device__ __half g_ah[(size_t)MROWS * DMODEL];
__device__ __half g_al[(size_t)MROWS * DMODEL];
__device__ __half g_qh[(size_t)MROWS * QKVDIM];   // rope'd qkv (fp16)

// ---------------- helpers ----------------
__device__ __forceinline__ uint32_t smem_to_u32(const void* smem_ptr) {
    uint32_t addr;
    asm("{ .reg .u64 tmp; cvta.to.shared.u64 tmp, %1; cvt.u32.u64 %0, tmp; }"
        : "=r"(addr) : "l"(smem_ptr));
    return addr;
}
__device__ __forceinline__ void cp_async16(uint32_t dst, const void* src) {
    asm volatile("cp.async.cg.shared.global [%0], [%1], 16;\n"
                 :: "r"(dst), "l"(src));
}
__device__ __forceinline__ void cp_commit() {
    asm volatile("cp.async.commit_group;\n" ::: "memory");
}
__device__ __forceinline__ void cp_wait1() {
    asm volatile("cp.async.wait_group 1;\n" ::: "memory");
}
__device__ __forceinline__ void cp_wait2() {
    asm volatile("cp.async.wait_group 2;\n" ::: "memory");
}
__device__ __forceinline__ void ldm_x4(uint32_t* r, uint32_t a) {
    asm volatile("ldmatrix.sync.aligned.m8n8.x4.shared.b16 {%0,%1,%2,%3}, [%4];"
                 : "=r"(r[0]), "=r"(r[1]), "=r"(r[2]), "=r"(r[3]) : "r"(a));
}
__device__ __forceinline__ void ldm_x4_t(uint32_t* r, uint32_t a) {
    asm volatile("ldmatrix.sync.aligned.m8n8.x4.trans.shared.b16 {%0,%1,%2,%3}, [%4];"
                 : "=r"(r[0]), "=r"(r[1]), "=r"(r[2]), "=r"(r[3]) : "r"(a));
}
__device__ __forceinline__ void mma_fp16(float* c, const uint32_t* a,
                                         uint32_t b0, uint32_t b1) {
    asm volatile(
        "mma.sync.aligned.m16n8k16.row.col.f32.f16.f16.f32 "
        "{%0,%1,%2,%3}, {%4,%5,%6,%7}, {%8,%9}, {%0,%1,%2,%3};"
        : "+f"(c[0]), "+f"(c[1]), "+f"(c[2]), "+f"(c[3])
        : "r"(a[0]), "r"(a[1]), "r"(a[2]), "r"(a[3]), "r"(b0), "r"(b1));
}
__device__ __forceinline__ float ex2f(float x) {
    float y;
    asm("ex2.approx.f32 %0, %1;" : "=f"(y) : "f"(x));
    return y;
}
__device__ __forceinline__ uint32_t pack_fp16(float f0, float f1) {
    uint16_t b0 = __half_as_ushort(__float2half_rn(f0));
    uint16_t b1 = __half_as_ushort(__float2half_rn(f1));
    return ((uint32_t)b1 << 16) | (uint32_t)b0;
}

// ============================================================
// HMMA GEMM (fp16 2-pass): C = (Ah+Al)[M,K] @ Bh[N,K]^T + bias
// 512 threads (16 warps, warp tile 64x32), CTA tile 128x256,
// BK=32, 3-stage cp.async pipeline, fp32 accum.
// ============================================================
#define HBM 128
#define HBN 256
#define HBK 32
#define ROWB 80
#define OFF_AH 0
#define OFF_AL 10240
#define OFF_BH 20480
#define STAGE_B 40960
#define HSMEM (3 * STAGE_B)      // 122880 bytes

__device__ __forceinline__ void gemm_load_stage(
    const __half* __restrict__ Ah, const __half* __restrict__ Al,
    const __half* __restrict__ Bh,
    uint32_t sbase, int bm, int bn, int k0, int K, int tid)
{
    #pragma unroll
    for (int l = 0; l < 2; l++) {
        int u = tid + l * 512;
        int half_ = u >> 9;
        int r = (u >> 2) & 127, g = u & 3;
        size_t goff = (size_t)(bm + r) * K + k0 + g * 8;
        cp_async16(sbase + (half_ ? OFF_AL : OFF_AH) + r * ROWB + g * 16,
                   (half_ ? Al : Ah) + goff);
    }
    #pragma unroll
    for (int l = 0; l < 2; l++) {
        int u = tid + l * 512;
        int r = (u >> 2) & 255, g = u & 3;
        size_t goff = (size_t)(bn + r) * K + k0 + g * 8;
        cp_async16(sbase + OFF_BH + r * ROWB + g * 16, Bh + goff);
    }
}

__global__ __launch_bounds__(512, 1) void hmma_gemm_kernel(
    const __half* __restrict__ Ah, const __half* __restrict__ Al,
    const __half* __restrict__ Bh,
    const float* __restrict__ bias, float* __restrict__ C,
    int M, int N, int K)
{
    extern __shared__ char smem[];
    const uint32_t sb = smem_to_u32(smem);
    const int tid = threadIdx.x;
    const int lane = tid & 31, wid = tid >> 5;
    const int wm = wid & 1;
    const int wn = wid >> 1;
    const int bm = blockIdx.y * HBM;
    const int bn = blockIdx.x * HBN;

    float acc[4][4][4];
    #pragma unroll
    for (int i = 0; i < 4; i++)
        #pragma unroll
        for (int j = 0; j < 4; j++)
            #pragma unroll
            for (int v = 0; v < 4; v++) acc[i][j][v] = 0.f;

    const int NC = K / HBK;

    gemm_load_stage(Ah, Al, Bh, sb, bm, bn, 0, K, tid);
    cp_commit();
    gemm_load_stage(Ah, Al, Bh, sb + STAGE_B, bm, bn, HBK, K, tid);
    cp_commit();

    int st = 0;
    for (int c = 0; c < NC; c++) {
        if (c + 2 < NC) {
            int st2 = st + 2; if (st2 >= 3) st2 -= 3;
            gemm_load_stage(Ah, Al, Bh, sb + st2 * STAGE_B,
                            bm, bn, (c + 2) * HBK, K, tid);
        }
        cp_commit();
        cp_wait2();
        __syncthreads();

        const uint32_t base = sb + st * STAGE_B;
        #pragma unroll
        for (int ks = 0; ks < 2; ks++) {
            const int kb = ks * 32 + ((lane >> 4) * 16);
            uint32_t a_addr = base + OFF_AH + (wm * 64 + (lane & 15)) * ROWB + kb;
            uint32_t b_addr = base + OFF_BH + (wn * 32 + (lane & 15)) * ROWB + kb;

            uint32_t A0[4][4], A1[4][4], B0[2][4];
            #pragma unroll
            for (int mt = 0; mt < 4; mt++) ldm_x4(A0[mt], a_addr + mt * 16 * ROWB);
            #pragma unroll
            for (int nb = 0; nb < 2; nb++) ldm_x4(B0[nb], b_addr + nb * 16 * ROWB);

            #pragma unroll
            for (int mt = 0; mt < 4; mt++)
                #pragma unroll
                for (int nb = 0; nb < 2; nb++) {
                    mma_fp16(acc[mt][2 * nb],     A0[mt], B0[nb][0], B0[nb][2]);
                    mma_fp16(acc[mt][2 * nb + 1], A0[mt], B0[nb][1], B0[nb][3]);
                }
            #pragma unroll
            for (int mt = 0; mt < 4; mt++)
                ldm_x4(A1[mt], a_addr + (OFF_AL - OFF_AH) + mt * 16 * ROWB);
            #pragma unroll
            for (int mt = 0; mt < 4; mt++)
                #pragma unroll
                for (int nb = 0; nb < 2; nb++) {
                    mma_fp16(acc[mt][2 * nb],     A1[mt], B0[nb][0], B0[nb][2]);
                    mma_fp16(acc[mt][2 * nb + 1], A1[mt], B0[nb][1], B0[nb][3]);
                }
        }
        __syncthreads();
        if (++st == 3) st = 0;
    }

    #pragma unroll
    for (int mt = 0; mt < 4; mt++) {
        const int row0 = bm + wm * 64 + mt * 16 + (lane >> 2);
        #pragma unroll
        for (int nt = 0; nt < 4; nt++) {
            const int col = bn + wn * 32 + nt * 8 + (lane & 3) * 2;
            const float b0 = bias[col], b1 = bias[col + 1];
            float2 v0 = make_float2(acc[mt][nt][0] + b0, acc[mt][nt][1] + b1);
            float2 v1 = make_float2(acc[mt][nt][2] + b0, acc[mt][nt][3] + b1);
            *(float2*)(C + (size_t)row0 * N + col) = v0;
            *(float2*)(C + (size_t)(row0 + 8) * N + col) = v1;
        }
    }
}

// ============================================================
// fp32 -> fp16 hi/lo split (activations)
// ============================================================
__global__ void split_fp16_kernel(const float* __restrict__ src,
                                  __half* __restrict__ hi,
                                  __half* __restrict__ lo, int n4)
{
    int i = blockIdx.x * blockDim.x + threadIdx.x;
    if (i >= n4) return;
    float4 v = ((const float4*)src)[i];
    __half h0 = __float2half_rn(v.x);
    __half h1 = __float2half_rn(v.y);
    __half h2 = __float2half_rn(v.z);
    __half h3 = __float2half_rn(v.w);
    __half l0 = __float2half_rn(v.x - __half2float(h0));
    __half l1 = __float2half_rn(v.y - __half2float(h1));
    __half l2 = __float2half_rn(v.z - __half2float(h2));
    __half l3 = __float2half_rn(v.w - __half2float(h3));
    __half2* hp = (__half2*)hi;
    __half2* lp = (__half2*)lo;
    hp[2 * i]     = __halves2half2(h0, h1);
    hp[2 * i + 1] = __halves2half2(h2, h3);
    lp[2 * i]     = __halves2half2(l0, l1);
    lp[2 * i + 1] = __halves2half2(l2, l3);
}

// fp32 -> fp16 (weights)
__global__ void convert_fp16_kernel(const float* __restrict__ src,
                                    __half* __restrict__ hi, int n4)
{
    int i = blockIdx.x * blockDim.x + threadIdx.x;
    if (i >= n4) return;
    float4 v = ((const float4*)src)[i];
    __half2* hp = (__half2*)hi;
    hp[2 * i]     = __halves2half2(__float2half_rn(v.x), __float2half_rn(v.y));
    hp[2 * i + 1] = __halves2half2(__float2half_rn(v.z), __float2half_rn(v.w));
}

// ============================================================
// RoPE+convert on q/k (fp16, hi only): one thread per (row, pair)
// ============================================================
__global__ void rope_split_qk_kernel(const float* __restrict__ qkv,
                                     __half* __restrict__ oh)
{
    int idx = blockIdx.x * blockDim.x + threadIdx.x;   // MROWS*64
    int p = idx & 63;
    int rowi = idx >> 6;
    if (rowi >= MROWS) return;
    int s = rowi & (SEQLEN - 1);

    float inv_freq = powf(10000.0f, -(float)(2 * p) / (float)HD);
    float ang = (float)s * inv_freq;
    float c, sn;
    sincosf(ang, &sn, &c);

    const float* row = qkv + (size_t)rowi * QKVDIM;
    __half* ohr = oh + (size_t)rowi * QKVDIM;

    #pragma unroll 4
    for (int hh = 0; hh < NHEADS + NKV; hh++) {
        int col = ((hh < NHEADS) ? hh * HD : QDIM + (hh - NHEADS) * HD) + 2 * p;
        float2 v = *(const float2*)(row + col);
        float r0 = v.x * c - v.y * sn;
        float r1 = v.x * sn + v.y * c;
        *(__half2*)(ohr + col) =
            __halves2half2(__float2half_rn(r0), __float2half_rn(r1));
    }
}

// convert-only for V region
__global__ void split_v_kernel(__half* __restrict__ oh)
{
    int idx = blockIdx.x * blockDim.x + threadIdx.x;   // MROWS*512 pairs
    int c2 = idx & 511;
    int rowi = idx >> 9;
    if (rowi >= MROWS) return;
    size_t off = (size_t)rowi * QKVDIM + QDIM + KVDIM + 2 * c2;
    float2 v = *(const float2*)(g_qkv + off);
    *(__half2*)(oh + off) =
        __halves2half2(__float2half_rn(v.x), __float2half_rn(v.y));
}

// ============================================================
// HMMA flash attention (fp16 single-pass):
// Br=128 (8 warps x 16 rows), Bc=64.
// scores = Qh·Kh ; O += Ph·Vh. Output -> fp16 hi/lo (exact split).
// ============================================================
#define QROWB 272
#define FA_QH  0
#define FA_ST0 34816
#define FA_STB 34816          // Kh + Vh per stage
#define FA_KH  0
#define FA_VH  17408
#define FA_SMEM (34816 + 2 * 34816)   // 104448

__global__ __launch_bounds__(256) void fa_hmma_kernel(
    const __half* __restrict__ qh,
    __half* __restrict__ oh, __half* __restrict__ ol)
{
    extern __shared__ char smem[];
    const uint32_t sb = smem_to_u32(smem);
    const int tid = threadIdx.x;
    const int lane = tid & 31, w = tid >> 5;
    const int b = blockIdx.z, h = blockIdx.y, qb = blockIdx.x;
    const int kvh = h >> 2;
    const int q0 = qb * 128;
    const int rowbase = b * SEQLEN;

    // Q tile: 128 rows x 16 chunks = 2048 -> 8 iters
    #pragma unroll
    for (int l = 0; l < 8; l++) {
        int u = tid + l * 256;
        int r = (u >> 4) & 127;
        int ch = u & 15;
        const __half* src = qh +
            (size_t)(rowbase + q0 + r) * QKVDIM + h * HD + ch * 8;
        cp_async16(sb + FA_QH + r * QROWB + ch * 16, src);
    }
    // KV stage: Kh + Vh = 2048 chunks -> 8 iters
    auto load_kv = [&](int t, int s) {
        const int k0 = t * 64;
        const uint32_t stb = sb + FA_ST0 + s * FA_STB;
        #pragma unroll
        for (int l = 0; l < 8; l++) {
            int u = tid + l * 256;
            int sel = u >> 10;            // 0 Kh, 1 Vh
            int r = (u >> 4) & 63;
            int ch = u & 15;
            int gcol = sel ? (QDIM + KVDIM + kvh * HD) : (QDIM + kvh * HD);
            const __half* src = qh +
                (size_t)(rowbase + k0 + r) * QKVDIM + gcol + ch * 8;
            cp_async16(stb + sel * 17408 + r * QROWB + ch * 16, src);
        }
    };

    const int tmax = 2 * qb + 2;
    load_kv(0, 0);
    cp_commit();

    const float CEXP = 0.12751742f;       // (1/sqrt(128)) * log2(e)
    float m2[2] = {-1e30f, -1e30f};
    float l2[2] = {0.f, 0.f};
    float O[16][4];
    #pragma unroll
    for (int i = 0; i < 16; i++)
        #pragma unroll
        for (int v = 0; v < 4; v++) O[i][v] = 0.f;

    const int qrow0 = q0 + w * 16;

    for (int t = 0; t < tmax; t++) {
        if (t + 1 < tmax) load_kv(t + 1, (t + 1) & 1);
        cp_commit();
        cp_wait1();
        __syncthreads();

        const int k0 = t * 64;
        const uint32_t stb = sb + FA_ST0 + (t & 1) * FA_STB;

        if (k0 <= qrow0 + 15) {
            // ---------- scores S = Qh Kh^T ----------
            float S[8][4];
            #pragma unroll
            for (int i = 0; i < 8; i++)
                #pragma unroll
                for (int v = 0; v < 4; v++) S[i][v] = 0.f;

            const uint32_t qa = sb + FA_QH + (w * 16 + (lane & 15)) * QROWB +
                                ((lane >> 4) * 16);
            const uint32_t ka = stb + FA_KH + ((lane & 15)) * QROWB +
                                ((lane >> 4) * 16);
            #pragma unroll
            for (int kc = 0; kc < 8; kc++) {
                uint32_t A0[4];
                ldm_x4(A0, qa + kc * 32);
                #pragma unroll
                for (int g = 0; g < 4; g++) {
                    uint32_t B[4];
                    ldm_x4(B, ka + kc * 32 + g * 16 * QROWB);
                    mma_fp16(S[2 * g],     A0, B[0], B[2]);
                    mma_fp16(S[2 * g + 1], A0, B[1], B[3]);
                }
            }

            // ---------- causal mask ----------
            if (k0 + 63 > qrow0) {
                const int r0 = qrow0 + (lane >> 2);
                #pragma unroll
                for (int nt = 0; nt < 8; nt++) {
                    const int c0 = k0 + nt * 8 + (lane & 3) * 2;
                    if (c0     > r0)     S[nt][0] = -1e30f;
                    if (c0 + 1 > r0)     S[nt][1] = -1e30f;
                    if (c0     > r0 + 8) S[nt][2] = -1e30f;
                    if (c0 + 1 > r0 + 8) S[nt][3] = -1e30f;
                }
            }

            // ---------- online softmax ----------
            #pragma unroll
            for (int r = 0; r < 2; r++) {
                const int i0 = r * 2;
                float rmax = -1e30f;
                #pragma unroll
                for (int nt = 0; nt < 8; nt++)
                    rmax = fmaxf(rmax, fmaxf(S[nt][i0], S[nt][i0 + 1]));
                rmax = fmaxf(rmax, __shfl_xor_sync(0xffffffffu, rmax, 1));
                rmax = fmaxf(rmax, __shfl_xor_sync(0xffffffffu, rmax, 2));
                const float mnew = fmaxf(m2[r], rmax);
                const float corr = ex2f((m2[r] - mnew) * CEXP);
                m2[r] = mnew;
                float psum = 0.f;
                #pragma unroll
                for (int nt = 0; nt < 8; nt++) {
                    float p0 = ex2f((S[nt][i0]     - mnew) * CEXP);
                    float p1 = ex2f((S[nt][i0 + 1] - mnew) * CEXP);
                    S[nt][i0] = p0; S[nt][i0 + 1] = p1;
                    psum += p0 + p1;
                }
                psum += __shfl_xor_sync(0xffffffffu, psum, 1);
                psum += __shfl_xor_sync(0xffffffffu, psum, 2);
                l2[r] = l2[r] * corr + psum;
                #pragma unroll
                for (int nt = 0; nt < 16; nt++) {
                    O[nt][i0]     *= corr;
                    O[nt][i0 + 1] *= corr;
                }
            }

            // ---------- PV: O += Ph Vh ----------
            #pragma unroll
            for (int j = 0; j < 4; j++) {
                uint32_t Ph[4];
                #pragma unroll
                for (int q = 0; q < 2; q++) {
                    const int nt = 2 * j + q;
                    Ph[2 * q]     = pack_fp16(S[nt][0], S[nt][1]);
                    Ph[2 * q + 1] = pack_fp16(S[nt][2], S[nt][3]);
                }
                const int vrow = j * 16 + (lane & 7) + ((lane >> 3) & 1) * 8;
                #pragma unroll
                for (int n = 0; n < 8; n++) {
                    uint32_t va = stb + FA_VH + vrow * QROWB +
                                  (n * 16 + (lane >> 4) * 8) * 2;
                    uint32_t Bv[4];
                    ldm_x4_t(Bv, va);
                    mma_fp16(O[2 * n],     Ph, Bv[0], Bv[1]);
                    mma_fp16(O[2 * n + 1], Ph, Bv[2], Bv[3]);
                }
            }
        }
        __syncthreads();
    }

    // ---------- epilogue: normalize, split to fp16 hi/lo ----------
    #pragma unroll
    for (int r = 0; r < 2; r++) {
        float inv = 1.0f / l2[r];
        const int row = rowbase + qrow0 + (lane >> 2) + r * 8;
        const size_t off = (size_t)row * DMODEL + h * HD + (lane & 3) * 2;
        #pragma unroll
        for (int nt = 0; nt < 16; nt++) {
            float f0 = O[nt][2 * r] * inv;
            float f1 = O[nt][2 * r + 1] * inv;
            uint32_t hi = pack_fp16(f0, f1);
            float g0 = f0 - __half2float(__float2half_rn(f0));
            float g1 = f1 - __half2float(__float2half_rn(f1));
            uint32_t lo = pack_fp16(g0, g1);
            *(uint32_t*)(oh + off + nt * 8) = hi;
            *(uint32_t*)(ol + off + nt * 8) = lo;
        }
    }
}

// ============================================================
// launch
// ============================================================
extern "C" void kernel_launch(void* const* d_in, const int* in_sizes, int n_in,
                              void* d_out, int out_size)
{
    (void)in_sizes; (void)n_in; (void)out_size;
    const float* x      = (const float*)d_in[0];
    const float* w_qkv  = (const float*)d_in[1];
    const float* b_qkv  = (const float*)d_in[2];
    const float* w_o    = (const float*)d_in[3];
    const float* b_o    = (const float*)d_in[4];
    float* out = (float*)d_out;

    float *qkv;
    __half *xh, *xl, *wqh, *woh, *ah, *al, *qh;
    cudaGetSymbolAddress((void**)&qkv, g_qkv);
    cudaGetSymbolAddress((void**)&xh,  g_xh);
    cudaGetSymbolAddress((void**)&xl,  g_xl);
    cudaGetSymbolAddress((void**)&wqh, g_wqkvh);
    cudaGetSymbolAddress((void**)&woh, g_woh);
    cudaGetSymbolAddress((void**)&ah,  g_ah);
    cudaGetSymbolAddress((void**)&al,  g_al);
    cudaGetSymbolAddress((void**)&qh,  g_qh);

    cudaFuncSetAttribute(hmma_gemm_kernel,
                         cudaFuncAttributeMaxDynamicSharedMemorySize, HSMEM);
    cudaFuncSetAttribute(fa_hmma_kernel,
                         cudaFuncAttributeMaxDynamicSharedMemorySize, FA_SMEM);

    // 0) split x (hi/lo); convert weights (fp16)
    {
        int n4 = (MROWS * DMODEL) / 4;
        split_fp16_kernel<<<n4 / 256, 256>>>(x, xh, xl, n4);
        int w4 = (QKVDIM * DMODEL) / 4;
        convert_fp16_kernel<<<w4 / 256, 256>>>(w_qkv, wqh, w4);
        int o4 = (DMODEL * DMODEL) / 4;
        convert_fp16_kernel<<<o4 / 256, 256>>>(w_o, woh, o4);
    }

    // 1) QKV projection (fp16 2-pass) -> fp32 g_qkv
    hmma_gemm_kernel<<<dim3(QKVDIM / HBN, MROWS / HBM), 512, HSMEM>>>(
        xh, xl, wqh, b_qkv, qkv, MROWS, QKVDIM, DMODEL);

    // 2) RoPE + convert to fp16
    rope_split_qk_kernel<<<(MROWS * 64) / 256, 256>>>(qkv, qh);
    split_v_kernel<<<(MROWS * 512) / 256, 256>>>(qh);

    // 3) fp16 flash attention -> g_ah/g_al (fp16 hi/lo)
    fa_hmma_kernel<<<dim3(SEQLEN / 128, NHEADS, BATCH), 256, FA_SMEM>>>(
        qh, ah, al);

    // 4) O projection (fp16 2-pass)
    hmma_gemm_kernel<<<dim3(DMODEL / HBN, MROWS / HBM), 512, HSMEM>>>(
        ah, al, woh, b_o, out, MROWS, DMODEL, DMODEL);
}

// round 11
// speedup vs baseline: 2.4984x; 1.6589x over previous
#include <cuda_runtime.h>
#include <cuda_fp16.h>
#include <math.h>
#include <stdint.h>

// ---------------- problem constants ----------------
#define BATCH   2
#define SEQLEN  2048
#define DMODEL  4096
#define NHEADS  32
#define NKV     8
#define HD      128
#define QDIM    (NHEADS * HD)            // 4096
#define KVDIM   (NKV * HD)               // 1024
#define QKVDIM  (QDIM + 2 * KVDIM)       // 6144
#define MROWS   (BATCH * SEQLEN)         // 4096

// ---------------- scratch (device globals: allocation-free) ----------------
__device__ float g_qkv[(size_t)MROWS * QKVDIM];
__device__ __half g_xh[(size_t)MROWS * DMODEL];
__device__ __half g_wqkvh[(size_t)QKVDIM * DMODEL];
__device__ __half g_woh[(size_t)DMODEL * DMODEL];
__device__ __half g_ah[(size_t)MROWS * DMODEL];
__device__ __half g_qh[(size_t)MROWS * QKVDIM];   // rope'd qkv (fp16)

// ---------------- helpers ----------------
__device__ __forceinline__ uint32_t smem_to_u32(const void* smem_ptr) {
    uint32_t addr;
    asm("{ .reg .u64 tmp; cvta.to.shared.u64 tmp, %1; cvt.u32.u64 %0, tmp; }"
        : "=r"(addr) : "l"(smem_ptr));
    return addr;
}
__device__ __forceinline__ void cp_async16(uint32_t dst, const void* src) {
    asm volatile("cp.async.cg.shared.global [%0], [%1], 16;\n"
                 :: "r"(dst), "l"(src));
}
__device__ __forceinline__ void cp_commit() {
    asm volatile("cp.async.commit_group;\n" ::: "memory");
}
__device__ __forceinline__ void cp_wait1() {
    asm volatile("cp.async.wait_group 1;\n" ::: "memory");
}
__device__ __forceinline__ void cp_wait2() {
    asm volatile("cp.async.wait_group 2;\n" ::: "memory");
}
__device__ __forceinline__ void ldm_x4(uint32_t* r, uint32_t a) {
    asm volatile("ldmatrix.sync.aligned.m8n8.x4.shared.b16 {%0,%1,%2,%3}, [%4];"
                 : "=r"(r[0]), "=r"(r[1]), "=r"(r[2]), "=r"(r[3]) : "r"(a));
}
__device__ __forceinline__ void ldm_x4_t(uint32_t* r, uint32_t a) {
    asm volatile("ldmatrix.sync.aligned.m8n8.x4.trans.shared.b16 {%0,%1,%2,%3}, [%4];"
                 : "=r"(r[0]), "=r"(r[1]), "=r"(r[2]), "=r"(r[3]) : "r"(a));
}
__device__ __forceinline__ void mma_fp16(float* c, const uint32_t* a,
                                         uint32_t b0, uint32_t b1) {
    asm volatile(
        "mma.sync.aligned.m16n8k16.row.col.f32.f16.f16.f32 "
        "{%0,%1,%2,%3}, {%4,%5,%6,%7}, {%8,%9}, {%0,%1,%2,%3};"
        : "+f"(c[0]), "+f"(c[1]), "+f"(c[2]), "+f"(c[3])
        : "r"(a[0]), "r"(a[1]), "r"(a[2]), "r"(a[3]), "r"(b0), "r"(b1));
}
__device__ __forceinline__ float ex2f(float x) {
    float y;
    asm("ex2.approx.f32 %0, %1;" : "=f"(y) : "f"(x));
    return y;
}
__device__ __forceinline__ uint32_t pack_fp16(float f0, float f1) {
    uint16_t b0 = __half_as_ushort(__float2half_rn(f0));
    uint16_t b1 = __half_as_ushort(__float2half_rn(f1));
    return ((uint32_t)b1 << 16) | (uint32_t)b0;
}

// ============================================================
// HMMA GEMM (fp16 single-pass): C = Ah[M,K] @ Bh[N,K]^T + bias
// 512 threads (16 warps, warp tile 64x32), CTA tile 128x256,
// BK=32, 3-stage cp.async pipeline, fp32 accum.
// ============================================================
#define HBM 128
#define HBN 256
#define HBK 32
#define ROWB 80
#define OFF_A  0
#define OFF_B  10240
#define STAGE_B 30720
#define HSMEM (3 * STAGE_B)      // 92160 bytes

__device__ __forceinline__ void gemm_load_stage(
    const __half* __restrict__ Ah, const __half* __restrict__ Bh,
    uint32_t sbase, int bm, int bn, int k0, int K, int tid)
{
    // A: 128 rows x 4 chunks = 512; 512 threads -> 1 iter
    {
        int r = (tid >> 2) & 127, g = tid & 3;
        size_t goff = (size_t)(bm + r) * K + k0 + g * 8;
        cp_async16(sbase + OFF_A + r * ROWB + g * 16, Ah + goff);
    }
    // B: 256 rows x 4 chunks = 1024 -> 2 iters
    #pragma unroll
    for (int l = 0; l < 2; l++) {
        int u = tid + l * 512;
        int r = (u >> 2) & 255, g = u & 3;
        size_t goff = (size_t)(bn + r) * K + k0 + g * 8;
        cp_async16(sbase + OFF_B + r * ROWB + g * 16, Bh + goff);
    }
}

__global__ __launch_bounds__(512, 1) void hmma_gemm_kernel(
    const __half* __restrict__ Ah, const __half* __restrict__ Bh,
    const float* __restrict__ bias, float* __restrict__ C,
    int M, int N, int K)
{
    extern __shared__ char smem[];
    const uint32_t sb = smem_to_u32(smem);
    const int tid = threadIdx.x;
    const int lane = tid & 31, wid = tid >> 5;
    const int wm = wid & 1;        // 2 warp rows (64 m each)
    const int wn = wid >> 1;       // 8 warp cols (32 n each)
    const int bm = blockIdx.y * HBM;
    const int bn = blockIdx.x * HBN;

    float acc[4][4][4];
    #pragma unroll
    for (int i = 0; i < 4; i++)
        #pragma unroll
        for (int j = 0; j < 4; j++)
            #pragma unroll
            for (int v = 0; v < 4; v++) acc[i][j][v] = 0.f;

    const int NC = K / HBK;

    gemm_load_stage(Ah, Bh, sb, bm, bn, 0, K, tid);
    cp_commit();
    gemm_load_stage(Ah, Bh, sb + STAGE_B, bm, bn, HBK, K, tid);
    cp_commit();

    int st = 0;
    for (int c = 0; c < NC; c++) {
        if (c + 2 < NC) {
            int st2 = st + 2; if (st2 >= 3) st2 -= 3;
            gemm_load_stage(Ah, Bh, sb + st2 * STAGE_B,
                            bm, bn, (c + 2) * HBK, K, tid);
        }
        cp_commit();
        cp_wait2();
        __syncthreads();

        const uint32_t base = sb + st * STAGE_B;
        #pragma unroll
        for (int ks = 0; ks < 2; ks++) {
            const int kb = ks * 32 + ((lane >> 4) * 16);
            uint32_t a_addr = base + OFF_A + (wm * 64 + (lane & 15)) * ROWB + kb;
            uint32_t b_addr = base + OFF_B + (wn * 32 + (lane & 15)) * ROWB + kb;

            uint32_t A0[4][4], B0[2][4];
            #pragma unroll
            for (int mt = 0; mt < 4; mt++) ldm_x4(A0[mt], a_addr + mt * 16 * ROWB);
            #pragma unroll
            for (int nb = 0; nb < 2; nb++) ldm_x4(B0[nb], b_addr + nb * 16 * ROWB);

            #pragma unroll
            for (int mt = 0; mt < 4; mt++)
                #pragma unroll
                for (int nb = 0; nb < 2; nb++) {
                    mma_fp16(acc[mt][2 * nb],     A0[mt], B0[nb][0], B0[nb][2]);
                    mma_fp16(acc[mt][2 * nb + 1], A0[mt], B0[nb][1], B0[nb][3]);
                }
        }
        __syncthreads();
        if (++st == 3) st = 0;
    }

    #pragma unroll
    for (int mt = 0; mt < 4; mt++) {
        const int row0 = bm + wm * 64 + mt * 16 + (lane >> 2);
        #pragma unroll
        for (int nt = 0; nt < 4; nt++) {
            const int col = bn + wn * 32 + nt * 8 + (lane & 3) * 2;
            const float b0 = bias[col], b1 = bias[col + 1];
            float2 v0 = make_float2(acc[mt][nt][0] + b0, acc[mt][nt][1] + b1);
            float2 v1 = make_float2(acc[mt][nt][2] + b0, acc[mt][nt][3] + b1);
            *(float2*)(C + (size_t)row0 * N + col) = v0;
            *(float2*)(C + (size_t)(row0 + 8) * N + col) = v1;
        }
    }
}

// ============================================================
// fp32 -> fp16 convert
// ============================================================
__global__ void convert_fp16_kernel(const float* __restrict__ src,
                                    __half* __restrict__ hi, int n4)
{
    int i = blockIdx.x * blockDim.x + threadIdx.x;
    if (i >= n4) return;
    float4 v = ((const float4*)src)[i];
    __half2* hp = (__half2*)hi;
    hp[2 * i]     = __halves2half2(__float2half_rn(v.x), __float2half_rn(v.y));
    hp[2 * i + 1] = __halves2half2(__float2half_rn(v.z), __float2half_rn(v.w));
}

// ============================================================
// RoPE+convert on q/k (fp16): one thread per (row, freq-pair)
// ============================================================
__global__ void rope_split_qk_kernel(const float* __restrict__ qkv,
                                     __half* __restrict__ oh)
{
    int idx = blockIdx.x * blockDim.x + threadIdx.x;   // MROWS*64
    int p = idx & 63;
    int rowi = idx >> 6;
    if (rowi >= MROWS) return;
    int s = rowi & (SEQLEN - 1);

    float inv_freq = powf(10000.0f, -(float)(2 * p) / (float)HD);
    float ang = (float)s * inv_freq;
    float c, sn;
    sincosf(ang, &sn, &c);

    const float* row = qkv + (size_t)rowi * QKVDIM;
    __half* ohr = oh + (size_t)rowi * QKVDIM;

    #pragma unroll 4
    for (int hh = 0; hh < NHEADS + NKV; hh++) {
        int col = ((hh < NHEADS) ? hh * HD : QDIM + (hh - NHEADS) * HD) + 2 * p;
        float2 v = *(const float2*)(row + col);
        float r0 = v.x * c - v.y * sn;
        float r1 = v.x * sn + v.y * c;
        *(__half2*)(ohr + col) =
            __halves2half2(__float2half_rn(r0), __float2half_rn(r1));
    }
}

// convert-only for V region
__global__ void split_v_kernel(__half* __restrict__ oh)
{
    int idx = blockIdx.x * blockDim.x + threadIdx.x;   // MROWS*512 pairs
    int c2 = idx & 511;
    int rowi = idx >> 9;
    if (rowi >= MROWS) return;
    size_t off = (size_t)rowi * QKVDIM + QDIM + KVDIM + 2 * c2;
    float2 v = *(const float2*)(g_qkv + off);
    *(__half2*)(oh + off) =
        __halves2half2(__float2half_rn(v.x), __float2half_rn(v.y));
}

// ============================================================
// HMMA flash attention (fp16 single-pass):
// Br=128 (8 warps x 16 rows), Bc=64.
// scores = Qh·Kh ; O += Ph·Vh. Output -> fp16.
// ============================================================
#define QROWB 272
#define FA_QH  0
#define FA_ST0 34816
#define FA_STB 34816          // Kh + Vh per stage
#define FA_KH  0
#define FA_VH  17408
#define FA_SMEM (34816 + 2 * 34816)   // 104448

__global__ __launch_bounds__(256) void fa_hmma_kernel(
    const __half* __restrict__ qh, __half* __restrict__ oh)
{
    extern __shared__ char smem[];
    const uint32_t sb = smem_to_u32(smem);
    const int tid = threadIdx.x;
    const int lane = tid & 31, w = tid >> 5;
    const int b = blockIdx.z, h = blockIdx.y, qb = blockIdx.x;
    const int kvh = h >> 2;
    const int q0 = qb * 128;
    const int rowbase = b * SEQLEN;

    // Q tile: 128 rows x 16 chunks = 2048 -> 8 iters
    #pragma unroll
    for (int l = 0; l < 8; l++) {
        int u = tid + l * 256;
        int r = (u >> 4) & 127;
        int ch = u & 15;
        const __half* src = qh +
            (size_t)(rowbase + q0 + r) * QKVDIM + h * HD + ch * 8;
        cp_async16(sb + FA_QH + r * QROWB + ch * 16, src);
    }
    // KV stage: Kh + Vh = 2048 chunks -> 8 iters
    auto load_kv = [&](int t, int s) {
        const int k0 = t * 64;
        const uint32_t stb = sb + FA_ST0 + s * FA_STB;
        #pragma unroll
        for (int l = 0; l < 8; l++) {
            int u = tid + l * 256;
            int sel = u >> 10;            // 0 Kh, 1 Vh
            int r = (u >> 4) & 63;
            int ch = u & 15;
            int gcol = sel ? (QDIM + KVDIM + kvh * HD) : (QDIM + kvh * HD);
            const __half* src = qh +
                (size_t)(rowbase + k0 + r) * QKVDIM + gcol + ch * 8;
            cp_async16(stb + sel * 17408 + r * QROWB + ch * 16, src);
        }
    };

    const int tmax = 2 * qb + 2;
    load_kv(0, 0);
    cp_commit();

    const float CEXP = 0.12751742f;       // (1/sqrt(128)) * log2(e)
    float m2[2] = {-1e30f, -1e30f};
    float l2[2] = {0.f, 0.f};
    float O[16][4];
    #pragma unroll
    for (int i = 0; i < 16; i++)
        #pragma unroll
        for (int v = 0; v < 4; v++) O[i][v] = 0.f;

    const int qrow0 = q0 + w * 16;

    for (int t = 0; t < tmax; t++) {
        if (t + 1 < tmax) load_kv(t + 1, (t + 1) & 1);
        cp_commit();
        cp_wait1();
        __syncthreads();

        const int k0 = t * 64;
        const uint32_t stb = sb + FA_ST0 + (t & 1) * FA_STB;

        if (k0 <= qrow0 + 15) {
            // ---------- scores S = Qh Kh^T ----------
            float S[8][4];
            #pragma unroll
            for (int i = 0; i < 8; i++)
                #pragma unroll
                for (int v = 0; v < 4; v++) S[i][v] = 0.f;

            const uint32_t qa = sb + FA_QH + (w * 16 + (lane & 15)) * QROWB +
                                ((lane >> 4) * 16);
            const uint32_t ka = stb + FA_KH + ((lane & 15)) * QROWB +
                                ((lane >> 4) * 16);
            #pragma unroll
            for (int kc = 0; kc < 8; kc++) {
                uint32_t A0[4];
                ldm_x4(A0, qa + kc * 32);
                #pragma unroll
                for (int g = 0; g < 4; g++) {
                    uint32_t B[4];
                    ldm_x4(B, ka + kc * 32 + g * 16 * QROWB);
                    mma_fp16(S[2 * g],     A0, B[0], B[2]);
                    mma_fp16(S[2 * g + 1], A0, B[1], B[3]);
                }
            }

            // ---------- causal mask ----------
            if (k0 + 63 > qrow0) {
                const int r0 = qrow0 + (lane >> 2);
                #pragma unroll
                for (int nt = 0; nt < 8; nt++) {
                    const int c0 = k0 + nt * 8 + (lane & 3) * 2;
                    if (c0     > r0)     S[nt][0] = -1e30f;
                    if (c0 + 1 > r0)     S[nt][1] = -1e30f;
                    if (c0     > r0 + 8) S[nt][2] = -1e30f;
                    if (c0 + 1 > r0 + 8) S[nt][3] = -1e30f;
                }
            }

            // ---------- online softmax ----------
            #pragma unroll
            for (int r = 0; r < 2; r++) {
                const int i0 = r * 2;
                float rmax = -1e30f;
                #pragma unroll
                for (int nt = 0; nt < 8; nt++)
                    rmax = fmaxf(rmax, fmaxf(S[nt][i0], S[nt][i0 + 1]));
                rmax = fmaxf(rmax, __shfl_xor_sync(0xffffffffu, rmax, 1));
                rmax = fmaxf(rmax, __shfl_xor_sync(0xffffffffu, rmax, 2));
                const float mnew = fmaxf(m2[r], rmax);
                const float corr = ex2f((m2[r] - mnew) * CEXP);
                m2[r] = mnew;
                float psum = 0.f;
                #pragma unroll
                for (int nt = 0; nt < 8; nt++) {
                    float p0 = ex2f((S[nt][i0]     - mnew) * CEXP);
                    float p1 = ex2f((S[nt][i0 + 1] - mnew) * CEXP);
                    S[nt][i0] = p0; S[nt][i0 + 1] = p1;
                    psum += p0 + p1;
                }
                psum += __shfl_xor_sync(0xffffffffu, psum, 1);
                psum += __shfl_xor_sync(0xffffffffu, psum, 2);
                l2[r] = l2[r] * corr + psum;
                #pragma unroll
                for (int nt = 0; nt < 16; nt++) {
                    O[nt][i0]     *= corr;
                    O[nt][i0 + 1] *= corr;
                }
            }

            // ---------- PV: O += Ph Vh ----------
            #pragma unroll
            for (int j = 0; j < 4; j++) {
                uint32_t Ph[4];
                #pragma unroll
                for (int q = 0; q < 2; q++) {
                    const int nt = 2 * j + q;
                    Ph[2 * q]     = pack_fp16(S[nt][0], S[nt][1]);
                    Ph[2 * q + 1] = pack_fp16(S[nt][2], S[nt][3]);
                }
                const int vrow = j * 16 + (lane & 7) + ((lane >> 3) & 1) * 8;
                #pragma unroll
                for (int n = 0; n < 8; n++) {
                    uint32_t va = stb + FA_VH + vrow * QROWB +
                                  (n * 16 + (lane >> 4) * 8) * 2;
                    uint32_t Bv[4];
                    ldm_x4_t(Bv, va);
                    mma_fp16(O[2 * n],     Ph, Bv[0], Bv[1]);
                    mma_fp16(O[2 * n + 1], Ph, Bv[2], Bv[3]);
                }
            }
        }
        __syncthreads();
    }

    // ---------- epilogue: normalize, convert to fp16 ----------
    #pragma unroll
    for (int r = 0; r < 2; r++) {
        float inv = 1.0f / l2[r];
        const int row = rowbase + qrow0 + (lane >> 2) + r * 8;
        const size_t off = (size_t)row * DMODEL + h * HD + (lane & 3) * 2;
        #pragma unroll
        for (int nt = 0; nt < 16; nt++) {
            float f0 = O[nt][2 * r] * inv;
            float f1 = O[nt][2 * r + 1] * inv;
            *(uint32_t*)(oh + off + nt * 8) = pack_fp16(f0, f1);
        }
    }
}

// ============================================================
// launch
// ============================================================
extern "C" void kernel_launch(void* const* d_in, const int* in_sizes, int n_in,
                              void* d_out, int out_size)
{
    (void)in_sizes; (void)n_in; (void)out_size;
    const float* x      = (const float*)d_in[0];
    const float* w_qkv  = (const float*)d_in[1];
    const float* b_qkv  = (const float*)d_in[2];
    const float* w_o    = (const float*)d_in[3];
    const float* b_o    = (const float*)d_in[4];
    float* out = (float*)d_out;

    float *qkv;
    __half *xh, *wqh, *woh, *ah, *qh;
    cudaGetSymbolAddress((void**)&qkv, g_qkv);
    cudaGetSymbolAddress((void**)&xh,  g_xh);
    cudaGetSymbolAddress((void**)&wqh, g_wqkvh);
    cudaGetSymbolAddress((void**)&woh, g_woh);
    cudaGetSymbolAddress((void**)&ah,  g_ah);
    cudaGetSymbolAddress((void**)&qh,  g_qh);

    cudaFuncSetAttribute(hmma_gemm_kernel,
                         cudaFuncAttributeMaxDynamicSharedMemorySize, HSMEM);
    cudaFuncSetAttribute(fa_hmma_kernel,
                         cudaFuncAttributeMaxDynamicSharedMemorySize, FA_SMEM);

    // 0) convert x and weights to fp16
    {
        int n4 = (MROWS * DMODEL) / 4;
        convert_fp16_kernel<<<n4 / 256, 256>>>(x, xh, n4);
        int w4 = (QKVDIM * DMODEL) / 4;
        convert_fp16_kernel<<<w4 / 256, 256>>>(w_qkv, wqh, w4);
        int o4 = (DMODEL * DMODEL) / 4;
        convert_fp16_kernel<<<o4 / 256, 256>>>(w_o, woh, o4);
    }

    // 1) QKV projection (fp16) -> fp32 g_qkv
    hmma_gemm_kernel<<<dim3(QKVDIM / HBN, MROWS / HBM), 512, HSMEM>>>(
        xh, wqh, b_qkv, qkv, MROWS, QKVDIM, DMODEL);

    // 2) RoPE + convert to fp16
    rope_split_qk_kernel<<<(MROWS * 64) / 256, 256>>>(qkv, qh);
    split_v_kernel<<<(MROWS * 512) / 256, 256>>>(qh);

    // 3) fp16 flash attention -> g_ah (fp16)
    fa_hmma_kernel<<<dim3(SEQLEN / 128, NHEADS, BATCH), 256, FA_SMEM>>>(
        qh, ah);

    // 4) O projection (fp16)
    hmma_gemm_kernel<<<dim3(DMODEL / HBN, MROWS / HBM), 512, HSMEM>>>(
        ah, woh, b_o, out, MROWS, DMODEL, DMODEL);
}

// round 12
// speedup vs baseline: 2.7886x; 1.1162x over previous
#include <cuda_runtime.h>
#include <cuda_fp16.h>
#include <math.h>
#include <stdint.h>

// ---------------- problem constants ----------------
#define BATCH   2
#define SEQLEN  2048
#define DMODEL  4096
#define NHEADS  32
#define NKV     8
#define HD      128
#define QDIM    (NHEADS * HD)            // 4096
#define KVDIM   (NKV * HD)               // 1024
#define QKVDIM  (QDIM + 2 * KVDIM)       // 6144
#define MROWS   (BATCH * SEQLEN)         // 4096

// ---------------- scratch (device globals: allocation-free) ----------------
__device__ __half g_xh[(size_t)MROWS * DMODEL];
__device__ __half g_wqkvh[(size_t)QKVDIM * DMODEL];
__device__ __half g_woh[(size_t)DMODEL * DMODEL];
__device__ __half g_ah[(size_t)MROWS * DMODEL];
__device__ __half g_qh[(size_t)MROWS * QKVDIM];   // rope'd qkv (fp16)

// ---------------- helpers ----------------
__device__ __forceinline__ uint32_t smem_to_u32(const void* smem_ptr) {
    uint32_t addr;
    asm("{ .reg .u64 tmp; cvta.to.shared.u64 tmp, %1; cvt.u32.u64 %0, tmp; }"
        : "=r"(addr) : "l"(smem_ptr));
    return addr;
}
__device__ __forceinline__ void cp_async16(uint32_t dst, const void* src) {
    asm volatile("cp.async.cg.shared.global [%0], [%1], 16;\n"
                 :: "r"(dst), "l"(src));
}
__device__ __forceinline__ void cp_commit() {
    asm volatile("cp.async.commit_group;\n" ::: "memory");
}
__device__ __forceinline__ void cp_wait1() {
    asm volatile("cp.async.wait_group 1;\n" ::: "memory");
}
__device__ __forceinline__ void ldm_x4(uint32_t* r, uint32_t a) {
    asm volatile("ldmatrix.sync.aligned.m8n8.x4.shared.b16 {%0,%1,%2,%3}, [%4];"
                 : "=r"(r[0]), "=r"(r[1]), "=r"(r[2]), "=r"(r[3]) : "r"(a));
}
__device__ __forceinline__ void ldm_x4_t(uint32_t* r, uint32_t a) {
    asm volatile("ldmatrix.sync.aligned.m8n8.x4.trans.shared.b16 {%0,%1,%2,%3}, [%4];"
                 : "=r"(r[0]), "=r"(r[1]), "=r"(r[2]), "=r"(r[3]) : "r"(a));
}
__device__ __forceinline__ void mma_fp16(float* c, const uint32_t* a,
                                         uint32_t b0, uint32_t b1) {
    asm volatile(
        "mma.sync.aligned.m16n8k16.row.col.f32.f16.f16.f32 "
        "{%0,%1,%2,%3}, {%4,%5,%6,%7}, {%8,%9}, {%0,%1,%2,%3};"
        : "+f"(c[0]), "+f"(c[1]), "+f"(c[2]), "+f"(c[3])
        : "r"(a[0]), "r"(a[1]), "r"(a[2]), "r"(a[3]), "r"(b0), "r"(b1));
}
__device__ __forceinline__ float ex2f(float x) {
    float y;
    asm("ex2.approx.f32 %0, %1;" : "=f"(y) : "f"(x));
    return y;
}
__device__ __forceinline__ uint32_t pack_fp16(float f0, float f1) {
    uint16_t b0 = __half_as_ushort(__float2half_rn(f0));
    uint16_t b1 = __half_as_ushort(__float2half_rn(f1));
    return ((uint32_t)b1 << 16) | (uint32_t)b0;
}

// ============================================================
// HMMA GEMM v4 (fp16): C = Ah[M,K] @ Bh[N,K]^T + bias
// 512 threads (16 warps, warp tile 64x32), CTA tile 128x256,
// BK=64, 3-stage cp.async pipeline, ONE barrier per chunk.
// FUSE_ROPE: epilogue applies bias+RoPE, writes fp16 (QKV path).
//      else: epilogue adds bias, writes fp32 (O projection).
// ============================================================
#define HBM 128
#define HBN 256
#define HBK 64
#define ROWB2 144                 // 64 halves (128B) + 16B pad
#define OFF_B (128 * ROWB2)       // 18432
#define STAGE_B ((128 + 256) * ROWB2)   // 55296
#define HSMEM (3 * STAGE_B)             // 165888

__device__ __forceinline__ void gemm_load_stage(
    const __half* __restrict__ Ah, const __half* __restrict__ Bh,
    uint32_t sbase, int bm, int bn, int k0, int K, int tid)
{
    // A: 128 rows x 8 16B-chunks = 1024 -> 2 iters of 512
    #pragma unroll
    for (int l = 0; l < 2; l++) {
        int u = tid + l * 512;
        int r = (u >> 3) & 127, g = u & 7;
        size_t goff = (size_t)(bm + r) * K + k0 + g * 8;
        cp_async16(sbase + r * ROWB2 + g * 16, Ah + goff);
    }
    // B: 256 rows x 8 chunks = 2048 -> 4 iters
    #pragma unroll
    for (int l = 0; l < 4; l++) {
        int u = tid + l * 512;
        int r = (u >> 3) & 255, g = u & 7;
        size_t goff = (size_t)(bn + r) * K + k0 + g * 8;
        cp_async16(sbase + OFF_B + r * ROWB2 + g * 16, Bh + goff);
    }
}

template <bool FUSE_ROPE>
__global__ __launch_bounds__(512, 1) void hmma_gemm_kernel(
    const __half* __restrict__ Ah, const __half* __restrict__ Bh,
    const float* __restrict__ bias,
    float* __restrict__ C32, __half* __restrict__ C16,
    int M, int N, int K)
{
    extern __shared__ char smem[];
    const uint32_t sb = smem_to_u32(smem);
    const int tid = threadIdx.x;
    const int lane = tid & 31, wid = tid >> 5;
    const int wm = wid & 1;        // 2 warp rows (64 m each)
    const int wn = wid >> 1;       // 8 warp cols (32 n each)
    const int bm = blockIdx.y * HBM;
    const int bn = blockIdx.x * HBN;

    float acc[4][4][4];
    #pragma unroll
    for (int i = 0; i < 4; i++)
        #pragma unroll
        for (int j = 0; j < 4; j++)
            #pragma unroll
            for (int v = 0; v < 4; v++) acc[i][j][v] = 0.f;

    const int NC = K / HBK;   // 64

    gemm_load_stage(Ah, Bh, sb, bm, bn, 0, K, tid);
    cp_commit();
    gemm_load_stage(Ah, Bh, sb + STAGE_B, bm, bn, HBK, K, tid);
    cp_commit();

    int st = 0;
    for (int c = 0; c < NC; c++) {
        cp_wait1();             // stage c resident
        __syncthreads();        // all warps see it; all done reading stage c+2's old data

        if (c + 2 < NC) {
            int st2 = st + 2; if (st2 >= 3) st2 -= 3;
            gemm_load_stage(Ah, Bh, sb + st2 * STAGE_B,
                            bm, bn, (c + 2) * HBK, K, tid);
            cp_commit();
        }

        const uint32_t base = sb + st * STAGE_B;
        const uint32_t a_row = base + (wm * 64 + (lane & 15)) * ROWB2 +
                               ((lane >> 4) * 16);
        const uint32_t b_row = base + OFF_B + (wn * 32 + (lane & 15)) * ROWB2 +
                               ((lane >> 4) * 16);
        #pragma unroll
        for (int ks = 0; ks < 4; ks++) {
            const int kb = ks * 32;
            uint32_t A0[4][4], B0[2][4];
            #pragma unroll
            for (int mt = 0; mt < 4; mt++)
                ldm_x4(A0[mt], a_row + kb + mt * 16 * ROWB2);
            #pragma unroll
            for (int nb = 0; nb < 2; nb++)
                ldm_x4(B0[nb], b_row + kb + nb * 16 * ROWB2);

            #pragma unroll
            for (int mt = 0; mt < 4; mt++)
                #pragma unroll
                for (int nb = 0; nb < 2; nb++) {
                    mma_fp16(acc[mt][2 * nb],     A0[mt], B0[nb][0], B0[nb][2]);
                    mma_fp16(acc[mt][2 * nb + 1], A0[mt], B0[nb][1], B0[nb][3]);
                }
        }
        if (++st == 3) st = 0;
    }

    // ---------------- epilogue ----------------
    #pragma unroll
    for (int mt = 0; mt < 4; mt++) {
        const int row0 = bm + wm * 64 + mt * 16 + (lane >> 2);
        #pragma unroll
        for (int nt = 0; nt < 4; nt++) {
            const int col = bn + wn * 32 + nt * 8 + (lane & 3) * 2;
            const float b0 = bias[col], b1 = bias[col + 1];
            float a0 = acc[mt][nt][0] + b0, a1 = acc[mt][nt][1] + b1;
            float a2 = acc[mt][nt][2] + b0, a3 = acc[mt][nt][3] + b1;
            if (FUSE_ROPE) {
                if (col < QDIM + KVDIM) {
                    const int p = (col & 127) >> 1;
                    // 10000^(-2p/128) = 2^(-(2p/128)*log2(10000))
                    const float inv_freq =
                        exp2f(-(float)(2 * p) * (13.287712379549449f / 128.f));
                    {
                        float s = (float)(row0 & (SEQLEN - 1));
                        float cc, sn; sincosf(s * inv_freq, &sn, &cc);
                        float r0 = a0 * cc - a1 * sn;
                        float r1 = a0 * sn + a1 * cc;
                        a0 = r0; a1 = r1;
                    }
                    {
                        float s = (float)((row0 + 8) & (SEQLEN - 1));
                        float cc, sn; sincosf(s * inv_freq, &sn, &cc);
                        float r0 = a2 * cc - a3 * sn;
                        float r1 = a2 * sn + a3 * cc;
                        a2 = r0; a3 = r1;
                    }
                }
                *(uint32_t*)(C16 + (size_t)row0 * N + col) = pack_fp16(a0, a1);
                *(uint32_t*)(C16 + (size_t)(row0 + 8) * N + col) = pack_fp16(a2, a3);
            } else {
                *(float2*)(C32 + (size_t)row0 * N + col) = make_float2(a0, a1);
                *(float2*)(C32 + (size_t)(row0 + 8) * N + col) = make_float2(a2, a3);
            }
        }
    }
}

// ============================================================
// fp32 -> fp16 convert
// ============================================================
__global__ void convert_fp16_kernel(const float* __restrict__ src,
                                    __half* __restrict__ hi, int n4)
{
    int i = blockIdx.x * blockDim.x + threadIdx.x;
    if (i >= n4) return;
    float4 v = ((const float4*)src)[i];
    __half2* hp = (__half2*)hi;
    hp[2 * i]     = __halves2half2(__float2half_rn(v.x), __float2half_rn(v.y));
    hp[2 * i + 1] = __halves2half2(__float2half_rn(v.z), __float2half_rn(v.w));
}

// ============================================================
// HMMA flash attention (fp16 single-pass):
// Br=128 (8 warps x 16 rows), Bc=64.
// scores = Qh·Kh ; O += Ph·Vh. Output -> fp16.
// ============================================================
#define QROWB 272
#define FA_QH  0
#define FA_ST0 34816
#define FA_STB 34816          // Kh + Vh per stage
#define FA_KH  0
#define FA_VH  17408
#define FA_SMEM (34816 + 2 * 34816)   // 104448

__global__ __launch_bounds__(256) void fa_hmma_kernel(
    const __half* __restrict__ qh, __half* __restrict__ oh)
{
    extern __shared__ char smem[];
    const uint32_t sb = smem_to_u32(smem);
    const int tid = threadIdx.x;
    const int lane = tid & 31, w = tid >> 5;
    const int b = blockIdx.z, h = blockIdx.y, qb = blockIdx.x;
    const int kvh = h >> 2;
    const int q0 = qb * 128;
    const int rowbase = b * SEQLEN;

    // Q tile: 128 rows x 16 chunks = 2048 -> 8 iters
    #pragma unroll
    for (int l = 0; l < 8; l++) {
        int u = tid + l * 256;
        int r = (u >> 4) & 127;
        int ch = u & 15;
        const __half* src = qh +
            (size_t)(rowbase + q0 + r) * QKVDIM + h * HD + ch * 8;
        cp_async16(sb + FA_QH + r * QROWB + ch * 16, src);
    }
    // KV stage: Kh + Vh = 2048 chunks -> 8 iters
    auto load_kv = [&](int t, int s) {
        const int k0 = t * 64;
        const uint32_t stb = sb + FA_ST0 + s * FA_STB;
        #pragma unroll
        for (int l = 0; l < 8; l++) {
            int u = tid + l * 256;
            int sel = u >> 10;            // 0 Kh, 1 Vh
            int r = (u >> 4) & 63;
            int ch = u & 15;
            int gcol = sel ? (QDIM + KVDIM + kvh * HD) : (QDIM + kvh * HD);
            const __half* src = qh +
                (size_t)(rowbase + k0 + r) * QKVDIM + gcol + ch * 8;
            cp_async16(stb + sel * 17408 + r * QROWB + ch * 16, src);
        }
    };

    const int tmax = 2 * qb + 2;
    load_kv(0, 0);
    cp_commit();

    const float CEXP = 0.12751742f;       // (1/sqrt(128)) * log2(e)
    float m2[2] = {-1e30f, -1e30f};
    float l2[2] = {0.f, 0.f};
    float O[16][4];
    #pragma unroll
    for (int i = 0; i < 16; i++)
        #pragma unroll
        for (int v = 0; v < 4; v++) O[i][v] = 0.f;

    const int qrow0 = q0 + w * 16;

    for (int t = 0; t < tmax; t++) {
        if (t + 1 < tmax) load_kv(t + 1, (t + 1) & 1);
        cp_commit();
        cp_wait1();
        __syncthreads();

        const int k0 = t * 64;
        const uint32_t stb = sb + FA_ST0 + (t & 1) * FA_STB;

        if (k0 <= qrow0 + 15) {
            // ---------- scores S = Qh Kh^T ----------
            float S[8][4];
            #pragma unroll
            for (int i = 0; i < 8; i++)
                #pragma unroll
                for (int v = 0; v < 4; v++) S[i][v] = 0.f;

            const uint32_t qa = sb + FA_QH + (w * 16 + (lane & 15)) * QROWB +
                                ((lane >> 4) * 16);
            const uint32_t ka = stb + FA_KH + ((lane & 15)) * QROWB +
                                ((lane >> 4) * 16);
            #pragma unroll
            for (int kc = 0; kc < 8; kc++) {
                uint32_t A0[4];
                ldm_x4(A0, qa + kc * 32);
                #pragma unroll
                for (int g = 0; g < 4; g++) {
                    uint32_t B[4];
                    ldm_x4(B, ka + kc * 32 + g * 16 * QROWB);
                    mma_fp16(S[2 * g],     A0, B[0], B[2]);
                    mma_fp16(S[2 * g + 1], A0, B[1], B[3]);
                }
            }

            // ---------- causal mask ----------
            if (k0 + 63 > qrow0) {
                const int r0 = qrow0 + (lane >> 2);
                #pragma unroll
                for (int nt = 0; nt < 8; nt++) {
                    const int c0 = k0 + nt * 8 + (lane & 3) * 2;
                    if (c0     > r0)     S[nt][0] = -1e30f;
                    if (c0 + 1 > r0)     S[nt][1] = -1e30f;
                    if (c0     > r0 + 8) S[nt][2] = -1e30f;
                    if (c0 + 1 > r0 + 8) S[nt][3] = -1e30f;
                }
            }

            // ---------- online softmax ----------
            #pragma unroll
            for (int r = 0; r < 2; r++) {
                const int i0 = r * 2;
                float rmax = -1e30f;
                #pragma unroll
                for (int nt = 0; nt < 8; nt++)
                    rmax = fmaxf(rmax, fmaxf(S[nt][i0], S[nt][i0 + 1]));
                rmax = fmaxf(rmax, __shfl_xor_sync(0xffffffffu, rmax, 1));
                rmax = fmaxf(rmax, __shfl_xor_sync(0xffffffffu, rmax, 2));
                const float mnew = fmaxf(m2[r], rmax);
                const float corr = ex2f((m2[r] - mnew) * CEXP);
                m2[r] = mnew;
                float psum = 0.f;
                #pragma unroll
                for (int nt = 0; nt < 8; nt++) {
                    float p0 = ex2f((S[nt][i0]     - mnew) * CEXP);
                    float p1 = ex2f((S[nt][i0 + 1] - mnew) * CEXP);
                    S[nt][i0] = p0; S[nt][i0 + 1] = p1;
                    psum += p0 + p1;
                }
                psum += __shfl_xor_sync(0xffffffffu, psum, 1);
                psum += __shfl_xor_sync(0xffffffffu, psum, 2);
                l2[r] = l2[r] * corr + psum;
                #pragma unroll
                for (int nt = 0; nt < 16; nt++) {
                    O[nt][i0]     *= corr;
                    O[nt][i0 + 1] *= corr;
                }
            }

            // ---------- PV: O += Ph Vh ----------
            #pragma unroll
            for (int j = 0; j < 4; j++) {
                uint32_t Ph[4];
                #pragma unroll
                for (int q = 0; q < 2; q++) {
                    const int nt = 2 * j + q;
                    Ph[2 * q]     = pack_fp16(S[nt][0], S[nt][1]);
                    Ph[2 * q + 1] = pack_fp16(S[nt][2], S[nt][3]);
                }
                const int vrow = j * 16 + (lane & 7) + ((lane >> 3) & 1) * 8;
                #pragma unroll
                for (int n = 0; n < 8; n++) {
                    uint32_t va = stb + FA_VH + vrow * QROWB +
                                  (n * 16 + (lane >> 4) * 8) * 2;
                    uint32_t Bv[4];
                    ldm_x4_t(Bv, va);
                    mma_fp16(O[2 * n],     Ph, Bv[0], Bv[1]);
                    mma_fp16(O[2 * n + 1], Ph, Bv[2], Bv[3]);
                }
            }
        }
        __syncthreads();
    }

    // ---------- epilogue: normalize, convert to fp16 ----------
    #pragma unroll
    for (int r = 0; r < 2; r++) {
        float inv = 1.0f / l2[r];
        const int row = rowbase + qrow0 + (lane >> 2) + r * 8;
        const size_t off = (size_t)row * DMODEL + h * HD + (lane & 3) * 2;
        #pragma unroll
        for (int nt = 0; nt < 16; nt++) {
            float f0 = O[nt][2 * r] * inv;
            float f1 = O[nt][2 * r + 1] * inv;
            *(uint32_t*)(oh + off + nt * 8) = pack_fp16(f0, f1);
        }
    }
}

// ============================================================
// launch
// ============================================================
extern "C" void kernel_launch(void* const* d_in, const int* in_sizes, int n_in,
                              void* d_out, int out_size)
{
    (void)in_sizes; (void)n_in; (void)out_size;
    const float* x      = (const float*)d_in[0];
    const float* w_qkv  = (const float*)d_in[1];
    const float* b_qkv  = (const float*)d_in[2];
    const float* w_o    = (const float*)d_in[3];
    const float* b_o    = (const float*)d_in[4];
    float* out = (float*)d_out;

    __half *xh, *wqh, *woh, *ah, *qh;
    cudaGetSymbolAddress((void**)&xh,  g_xh);
    cudaGetSymbolAddress((void**)&wqh, g_wqkvh);
    cudaGetSymbolAddress((void**)&woh, g_woh);
    cudaGetSymbolAddress((void**)&ah,  g_ah);
    cudaGetSymbolAddress((void**)&qh,  g_qh);

    cudaFuncSetAttribute(hmma_gemm_kernel<true>,
                         cudaFuncAttributeMaxDynamicSharedMemorySize, HSMEM);
    cudaFuncSetAttribute(hmma_gemm_kernel<false>,
                         cudaFuncAttributeMaxDynamicSharedMemorySize, HSMEM);
    cudaFuncSetAttribute(fa_hmma_kernel,
                         cudaFuncAttributeMaxDynamicSharedMemorySize, FA_SMEM);

    // 0) convert x and weights to fp16
    {
        int n4 = (MROWS * DMODEL) / 4;
        convert_fp16_kernel<<<n4 / 256, 256>>>(x, xh, n4);
        int w4 = (QKVDIM * DMODEL) / 4;
        convert_fp16_kernel<<<w4 / 256, 256>>>(w_qkv, wqh, w4);
        int o4 = (DMODEL * DMODEL) / 4;
        convert_fp16_kernel<<<o4 / 256, 256>>>(w_o, woh, o4);
    }

    // 1) QKV projection + fused bias/RoPE/fp16 -> g_qh
    hmma_gemm_kernel<true><<<dim3(QKVDIM / HBN, MROWS / HBM), 512, HSMEM>>>(
        xh, wqh, b_qkv, nullptr, qh, MROWS, QKVDIM, DMODEL);

    // 2) fp16 flash attention -> g_ah (fp16)
    fa_hmma_kernel<<<dim3(SEQLEN / 128, NHEADS, BATCH), 256, FA_SMEM>>>(
        qh, ah);

    // 3) O projection (fp16) -> fp32 out
    hmma_gemm_kernel<false><<<dim3(DMODEL / HBN, MROWS / HBM), 512, HSMEM>>>(
        ah, woh, b_o, out, nullptr, MROWS, DMODEL, DMODEL);
}

// round 13
// speedup vs baseline: 3.0545x; 1.0953x over previous
#include <cuda_runtime.h>
#include <cuda_fp16.h>
#include <math.h>
#include <stdint.h>

// ---------------- problem constants ----------------
#define BATCH   2
#define SEQLEN  2048
#define DMODEL  4096
#define NHEADS  32
#define NKV     8
#define HD      128
#define QDIM    (NHEADS * HD)            // 4096
#define KVDIM   (NKV * HD)               // 1024
#define QKVDIM  (QDIM + 2 * KVDIM)       // 6144
#define MROWS   (BATCH * SEQLEN)         // 4096

// ---------------- scratch (device globals: allocation-free) ----------------
__device__ __half g_xh[(size_t)MROWS * DMODEL];
__device__ __half g_wqkvh[(size_t)QKVDIM * DMODEL];
__device__ __half g_woh[(size_t)DMODEL * DMODEL];
__device__ __half g_ah[(size_t)MROWS * DMODEL];
__device__ __half g_qh[(size_t)MROWS * QKVDIM];   // rope'd qkv (fp16)

// ---------------- helpers ----------------
__device__ __forceinline__ uint32_t smem_to_u32(const void* smem_ptr) {
    uint32_t addr;
    asm("{ .reg .u64 tmp; cvta.to.shared.u64 tmp, %1; cvt.u32.u64 %0, tmp; }"
        : "=r"(addr) : "l"(smem_ptr));
    return addr;
}
__device__ __forceinline__ void cp_async16(uint32_t dst, const void* src) {
    asm volatile("cp.async.cg.shared.global [%0], [%1], 16;\n"
                 :: "r"(dst), "l"(src));
}
__device__ __forceinline__ void cp_commit() {
    asm volatile("cp.async.commit_group;\n" ::: "memory");
}
__device__ __forceinline__ void cp_wait0() {
    asm volatile("cp.async.wait_group 0;\n" ::: "memory");
}
__device__ __forceinline__ void cp_wait1() {
    asm volatile("cp.async.wait_group 1;\n" ::: "memory");
}
__device__ __forceinline__ void ldm_x4(uint32_t* r, uint32_t a) {
    asm volatile("ldmatrix.sync.aligned.m8n8.x4.shared.b16 {%0,%1,%2,%3}, [%4];"
                 : "=r"(r[0]), "=r"(r[1]), "=r"(r[2]), "=r"(r[3]) : "r"(a));
}
__device__ __forceinline__ void ldm_x4_t(uint32_t* r, uint32_t a) {
    asm volatile("ldmatrix.sync.aligned.m8n8.x4.trans.shared.b16 {%0,%1,%2,%3}, [%4];"
                 : "=r"(r[0]), "=r"(r[1]), "=r"(r[2]), "=r"(r[3]) : "r"(a));
}
__device__ __forceinline__ void mma_fp16(float* c, const uint32_t* a,
                                         uint32_t b0, uint32_t b1) {
    asm volatile(
        "mma.sync.aligned.m16n8k16.row.col.f32.f16.f16.f32 "
        "{%0,%1,%2,%3}, {%4,%5,%6,%7}, {%8,%9}, {%0,%1,%2,%3};"
        : "+f"(c[0]), "+f"(c[1]), "+f"(c[2]), "+f"(c[3])
        : "r"(a[0]), "r"(a[1]), "r"(a[2]), "r"(a[3]), "r"(b0), "r"(b1));
}
__device__ __forceinline__ float ex2f(float x) {
    float y;
    asm("ex2.approx.f32 %0, %1;" : "=f"(y) : "f"(x));
    return y;
}
__device__ __forceinline__ uint32_t pack_fp16(float f0, float f1) {
    uint16_t b0 = __half_as_ushort(__float2half_rn(f0));
    uint16_t b1 = __half_as_ushort(__float2half_rn(f1));
    return ((uint32_t)b1 << 16) | (uint32_t)b0;
}

// ============================================================
// HMMA GEMM v5 (fp16): C = Ah[M,K] @ Bh[N,K]^T + bias
// 256 threads (8 warps, warp tile 64x32), CTA tile 128x128,
// BK=64, 3-stage cp.async pipeline, 2 CTAs per SM.
// FUSE_ROPE: epilogue applies bias+RoPE, writes fp16 (QKV path).
//      else: epilogue adds bias, writes fp32 (O projection).
// ============================================================
#define HBM 128
#define HBN 128
#define HBK 64
#define ROWB2 144                       // 64 halves (128B) + 16B pad
#define OFF_B (128 * ROWB2)             // 18432
#define STAGE_B (256 * ROWB2)           // 36864
#define HSMEM (3 * STAGE_B)             // 110592

__device__ __forceinline__ void gemm_load_stage(
    const __half* __restrict__ Ah, const __half* __restrict__ Bh,
    uint32_t sbase, int bm, int bn, int k0, int K, int tid)
{
    // A: 128 rows x 8 16B-chunks = 1024 -> 4 iters of 256
    #pragma unroll
    for (int l = 0; l < 4; l++) {
        int u = tid + l * 256;
        int r = (u >> 3) & 127, g = u & 7;
        size_t goff = (size_t)(bm + r) * K + k0 + g * 8;
        cp_async16(sbase + r * ROWB2 + g * 16, Ah + goff);
    }
    // B: 128 rows x 8 chunks = 1024 -> 4 iters
    #pragma unroll
    for (int l = 0; l < 4; l++) {
        int u = tid + l * 256;
        int r = (u >> 3) & 127, g = u & 7;
        size_t goff = (size_t)(bn + r) * K + k0 + g * 8;
        cp_async16(sbase + OFF_B + r * ROWB2 + g * 16, Bh + goff);
    }
}

template <bool FUSE_ROPE>
__global__ __launch_bounds__(256, 2) void hmma_gemm_kernel(
    const __half* __restrict__ Ah, const __half* __restrict__ Bh,
    const float* __restrict__ bias,
    float* __restrict__ C32, __half* __restrict__ C16,
    int M, int N, int K)
{
    extern __shared__ char smem[];
    const uint32_t sb = smem_to_u32(smem);
    const int tid = threadIdx.x;
    const int lane = tid & 31, wid = tid >> 5;
    const int wm = wid & 1;        // 2 warp rows (64 m each)
    const int wn = wid >> 1;       // 4 warp cols (32 n each)
    const int bm = blockIdx.y * HBM;
    const int bn = blockIdx.x * HBN;

    float acc[4][4][4];
    #pragma unroll
    for (int i = 0; i < 4; i++)
        #pragma unroll
        for (int j = 0; j < 4; j++)
            #pragma unroll
            for (int v = 0; v < 4; v++) acc[i][j][v] = 0.f;

    const int NC = K / HBK;   // 64

    gemm_load_stage(Ah, Bh, sb, bm, bn, 0, K, tid);
    cp_commit();
    gemm_load_stage(Ah, Bh, sb + STAGE_B, bm, bn, HBK, K, tid);
    cp_commit();

    int st = 0;
    for (int c = 0; c < NC; c++) {
        if (c + 2 < NC) cp_wait1(); else cp_wait0();  // stage c resident
        __syncthreads();        // all warps done reading stage c+2's old data

        if (c + 2 < NC) {
            int st2 = st + 2; if (st2 >= 3) st2 -= 3;
            gemm_load_stage(Ah, Bh, sb + st2 * STAGE_B,
                            bm, bn, (c + 2) * HBK, K, tid);
            cp_commit();
        }

        const uint32_t base = sb + st * STAGE_B;
        const uint32_t a_row = base + (wm * 64 + (lane & 15)) * ROWB2 +
                               ((lane >> 4) * 16);
        const uint32_t b_row = base + OFF_B + (wn * 32 + (lane & 15)) * ROWB2 +
                               ((lane >> 4) * 16);
        #pragma unroll
        for (int ks = 0; ks < 4; ks++) {
            const int kb = ks * 32;
            uint32_t A0[4][4], B0[2][4];
            #pragma unroll
            for (int mt = 0; mt < 4; mt++)
                ldm_x4(A0[mt], a_row + kb + mt * 16 * ROWB2);
            #pragma unroll
            for (int nb = 0; nb < 2; nb++)
                ldm_x4(B0[nb], b_row + kb + nb * 16 * ROWB2);

            #pragma unroll
            for (int mt = 0; mt < 4; mt++)
                #pragma unroll
                for (int nb = 0; nb < 2; nb++) {
                    mma_fp16(acc[mt][2 * nb],     A0[mt], B0[nb][0], B0[nb][2]);
                    mma_fp16(acc[mt][2 * nb + 1], A0[mt], B0[nb][1], B0[nb][3]);
                }
        }
        if (++st == 3) st = 0;
    }

    // ---------------- epilogue ----------------
    #pragma unroll
    for (int mt = 0; mt < 4; mt++) {
        const int row0 = bm + wm * 64 + mt * 16 + (lane >> 2);
        #pragma unroll
        for (int nt = 0; nt < 4; nt++) {
            const int col = bn + wn * 32 + nt * 8 + (lane & 3) * 2;
            const float b0 = bias[col], b1 = bias[col + 1];
            float a0 = acc[mt][nt][0] + b0, a1 = acc[mt][nt][1] + b1;
            float a2 = acc[mt][nt][2] + b0, a3 = acc[mt][nt][3] + b1;
            if (FUSE_ROPE) {
                if (col < QDIM + KVDIM) {
                    const int p = (col & 127) >> 1;
                    // 10000^(-2p/128) = 2^(-(2p/128)*log2(10000))
                    const float inv_freq =
                        exp2f(-(float)(2 * p) * (13.287712379549449f / 128.f));
                    {
                        float s = (float)(row0 & (SEQLEN - 1));
                        float cc, sn; sincosf(s * inv_freq, &sn, &cc);
                        float r0 = a0 * cc - a1 * sn;
                        float r1 = a0 * sn + a1 * cc;
                        a0 = r0; a1 = r1;
                    }
                    {
                        float s = (float)((row0 + 8) & (SEQLEN - 1));
                        float cc, sn; sincosf(s * inv_freq, &sn, &cc);
                        float r0 = a2 * cc - a3 * sn;
                        float r1 = a2 * sn + a3 * cc;
                        a2 = r0; a3 = r1;
                    }
                }
                *(uint32_t*)(C16 + (size_t)row0 * N + col) = pack_fp16(a0, a1);
                *(uint32_t*)(C16 + (size_t)(row0 + 8) * N + col) = pack_fp16(a2, a3);
            } else {
                *(float2*)(C32 + (size_t)row0 * N + col) = make_float2(a0, a1);
                *(float2*)(C32 + (size_t)(row0 + 8) * N + col) = make_float2(a2, a3);
            }
        }
    }
}

// ============================================================
// fp32 -> fp16 convert
// ============================================================
__global__ void convert_fp16_kernel(const float* __restrict__ src,
                                    __half* __restrict__ hi, int n4)
{
    int i = blockIdx.x * blockDim.x + threadIdx.x;
    if (i >= n4) return;
    float4 v = ((const float4*)src)[i];
    __half2* hp = (__half2*)hi;
    hp[2 * i]     = __halves2half2(__float2half_rn(v.x), __float2half_rn(v.y));
    hp[2 * i + 1] = __halves2half2(__float2half_rn(v.z), __float2half_rn(v.w));
}

// ============================================================
// HMMA flash attention (fp16 single-pass):
// Br=128 (8 warps x 16 rows), Bc=64.
// scores = Qh·Kh ; O += Ph·Vh. Output -> fp16.
// ============================================================
#define QROWB 272
#define FA_QH  0
#define FA_ST0 34816
#define FA_STB 34816          // Kh + Vh per stage
#define FA_KH  0
#define FA_VH  17408
#define FA_SMEM (34816 + 2 * 34816)   // 104448

__global__ __launch_bounds__(256) void fa_hmma_kernel(
    const __half* __restrict__ qh, __half* __restrict__ oh)
{
    extern __shared__ char smem[];
    const uint32_t sb = smem_to_u32(smem);
    const int tid = threadIdx.x;
    const int lane = tid & 31, w = tid >> 5;
    const int b = blockIdx.z, h = blockIdx.y, qb = blockIdx.x;
    const int kvh = h >> 2;
    const int q0 = qb * 128;
    const int rowbase = b * SEQLEN;

    // Q tile: 128 rows x 16 chunks = 2048 -> 8 iters
    #pragma unroll
    for (int l = 0; l < 8; l++) {
        int u = tid + l * 256;
        int r = (u >> 4) & 127;
        int ch = u & 15;
        const __half* src = qh +
            (size_t)(rowbase + q0 + r) * QKVDIM + h * HD + ch * 8;
        cp_async16(sb + FA_QH + r * QROWB + ch * 16, src);
    }
    // KV stage: Kh + Vh = 2048 chunks -> 8 iters
    auto load_kv = [&](int t, int s) {
        const int k0 = t * 64;
        const uint32_t stb = sb + FA_ST0 + s * FA_STB;
        #pragma unroll
        for (int l = 0; l < 8; l++) {
            int u = tid + l * 256;
            int sel = u >> 10;            // 0 Kh, 1 Vh
            int r = (u >> 4) & 63;
            int ch = u & 15;
            int gcol = sel ? (QDIM + KVDIM + kvh * HD) : (QDIM + kvh * HD);
            const __half* src = qh +
                (size_t)(rowbase + k0 + r) * QKVDIM + gcol + ch * 8;
            cp_async16(stb + sel * 17408 + r * QROWB + ch * 16, src);
        }
    };

    const int tmax = 2 * qb + 2;
    load_kv(0, 0);
    cp_commit();

    const float CEXP = 0.12751742f;       // (1/sqrt(128)) * log2(e)
    float m2[2] = {-1e30f, -1e30f};
    float l2[2] = {0.f, 0.f};
    float O[16][4];
    #pragma unroll
    for (int i = 0; i < 16; i++)
        #pragma unroll
        for (int v = 0; v < 4; v++) O[i][v] = 0.f;

    const int qrow0 = q0 + w * 16;

    for (int t = 0; t < tmax; t++) {
        if (t + 1 < tmax) load_kv(t + 1, (t + 1) & 1);
        cp_commit();
        cp_wait1();
        __syncthreads();

        const int k0 = t * 64;
        const uint32_t stb = sb + FA_ST0 + (t & 1) * FA_STB;

        if (k0 <= qrow0 + 15) {
            // ---------- scores S = Qh Kh^T ----------
            float S[8][4];
            #pragma unroll
            for (int i = 0; i < 8; i++)
                #pragma unroll
                for (int v = 0; v < 4; v++) S[i][v] = 0.f;

            const uint32_t qa = sb + FA_QH + (w * 16 + (lane & 15)) * QROWB +
                                ((lane >> 4) * 16);
            const uint32_t ka = stb + FA_KH + ((lane & 15)) * QROWB +
                                ((lane >> 4) * 16);
            #pragma unroll
            for (int kc = 0; kc < 8; kc++) {
                uint32_t A0[4];
                ldm_x4(A0, qa + kc * 32);
                #pragma unroll
                for (int g = 0; g < 4; g++) {
                    uint32_t B[4];
                    ldm_x4(B, ka + kc * 32 + g * 16 * QROWB);
                    mma_fp16(S[2 * g],     A0, B[0], B[2]);
                    mma_fp16(S[2 * g + 1], A0, B[1], B[3]);
                }
            }

            // ---------- causal mask ----------
            if (k0 + 63 > qrow0) {
                const int r0 = qrow0 + (lane >> 2);
                #pragma unroll
                for (int nt = 0; nt < 8; nt++) {
                    const int c0 = k0 + nt * 8 + (lane & 3) * 2;
                    if (c0     > r0)     S[nt][0] = -1e30f;
                    if (c0 + 1 > r0)     S[nt][1] = -1e30f;
                    if (c0     > r0 + 8) S[nt][2] = -1e30f;
                    if (c0 + 1 > r0 + 8) S[nt][3] = -1e30f;
                }
            }

            // ---------- online softmax ----------
            #pragma unroll
            for (int r = 0; r < 2; r++) {
                const int i0 = r * 2;
                float rmax = -1e30f;
                #pragma unroll
                for (int nt = 0; nt < 8; nt++)
                    rmax = fmaxf(rmax, fmaxf(S[nt][i0], S[nt][i0 + 1]));
                rmax = fmaxf(rmax, __shfl_xor_sync(0xffffffffu, rmax, 1));
                rmax = fmaxf(rmax, __shfl_xor_sync(0xffffffffu, rmax, 2));
                const float mnew = fmaxf(m2[r], rmax);
                const float corr = ex2f((m2[r] - mnew) * CEXP);
                m2[r] = mnew;
                float psum = 0.f;
                #pragma unroll
                for (int nt = 0; nt < 8; nt++) {
                    float p0 = ex2f((S[nt][i0]     - mnew) * CEXP);
                    float p1 = ex2f((S[nt][i0 + 1] - mnew) * CEXP);
                    S[nt][i0] = p0; S[nt][i0 + 1] = p1;
                    psum += p0 + p1;
                }
                psum += __shfl_xor_sync(0xffffffffu, psum, 1);
                psum += __shfl_xor_sync(0xffffffffu, psum, 2);
                l2[r] = l2[r] * corr + psum;
                #pragma unroll
                for (int nt = 0; nt < 16; nt++) {
                    O[nt][i0]     *= corr;
                    O[nt][i0 + 1] *= corr;
                }
            }

            // ---------- PV: O += Ph Vh ----------
            #pragma unroll
            for (int j = 0; j < 4; j++) {
                uint32_t Ph[4];
                #pragma unroll
                for (int q = 0; q < 2; q++) {
                    const int nt = 2 * j + q;
                    Ph[2 * q]     = pack_fp16(S[nt][0], S[nt][1]);
                    Ph[2 * q + 1] = pack_fp16(S[nt][2], S[nt][3]);
                }
                const int vrow = j * 16 + (lane & 7) + ((lane >> 3) & 1) * 8;
                #pragma unroll
                for (int n = 0; n < 8; n++) {
                    uint32_t va = stb + FA_VH + vrow * QROWB +
                                  (n * 16 + (lane >> 4) * 8) * 2;
                    uint32_t Bv[4];
                    ldm_x4_t(Bv, va);
                    mma_fp16(O[2 * n],     Ph, Bv[0], Bv[1]);
                    mma_fp16(O[2 * n + 1], Ph, Bv[2], Bv[3]);
                }
            }
        }
        __syncthreads();
    }

    // ---------- epilogue: normalize, convert to fp16 ----------
    #pragma unroll
    for (int r = 0; r < 2; r++) {
        float inv = 1.0f / l2[r];
        const int row = rowbase + qrow0 + (lane >> 2) + r * 8;
        const size_t off = (size_t)row * DMODEL + h * HD + (lane & 3) * 2;
        #pragma unroll
        for (int nt = 0; nt < 16; nt++) {
            float f0 = O[nt][2 * r] * inv;
            float f1 = O[nt][2 * r + 1] * inv;
            *(uint32_t*)(oh + off + nt * 8) = pack_fp16(f0, f1);
        }
    }
}

// ============================================================
// launch
// ============================================================
extern "C" void kernel_launch(void* const* d_in, const int* in_sizes, int n_in,
                              void* d_out, int out_size)
{
    (void)in_sizes; (void)n_in; (void)out_size;
    const float* x      = (const float*)d_in[0];
    const float* w_qkv  = (const float*)d_in[1];
    const float* b_qkv  = (const float*)d_in[2];
    const float* w_o    = (const float*)d_in[3];
    const float* b_o    = (const float*)d_in[4];
    float* out = (float*)d_out;

    __half *xh, *wqh, *woh, *ah, *qh;
    cudaGetSymbolAddress((void**)&xh,  g_xh);
    cudaGetSymbolAddress((void**)&wqh, g_wqkvh);
    cudaGetSymbolAddress((void**)&woh, g_woh);
    cudaGetSymbolAddress((void**)&ah,  g_ah);
    cudaGetSymbolAddress((void**)&qh,  g_qh);

    cudaFuncSetAttribute(hmma_gemm_kernel<true>,
                         cudaFuncAttributeMaxDynamicSharedMemorySize, HSMEM);
    cudaFuncSetAttribute(hmma_gemm_kernel<false>,
                         cudaFuncAttributeMaxDynamicSharedMemorySize, HSMEM);
    cudaFuncSetAttribute(fa_hmma_kernel,
                         cudaFuncAttributeMaxDynamicSharedMemorySize, FA_SMEM);

    // 0) convert x and weights to fp16
    {
        int n4 = (MROWS * DMODEL) / 4;
        convert_fp16_kernel<<<n4 / 256, 256>>>(x, xh, n4);
        int w4 = (QKVDIM * DMODEL) / 4;
        convert_fp16_kernel<<<w4 / 256, 256>>>(w_qkv, wqh, w4);
        int o4 = (DMODEL * DMODEL) / 4;
        convert_fp16_kernel<<<o4 / 256, 256>>>(w_o, woh, o4);
    }

    // 1) QKV projection + fused bias/RoPE/fp16 -> g_qh
    hmma_gemm_kernel<true><<<dim3(QKVDIM / HBN, MROWS / HBM), 256, HSMEM>>>(
        xh, wqh, b_qkv, nullptr, qh, MROWS, QKVDIM, DMODEL);

    // 2) fp16 flash attention -> g_ah (fp16)
    fa_hmma_kernel<<<dim3(SEQLEN / 128, NHEADS, BATCH), 256, FA_SMEM>>>(
        qh, ah);

    // 3) O projection (fp16) -> fp32 out
    hmma_gemm_kernel<false><<<dim3(DMODEL / HBN, MROWS / HBM), 256, HSMEM>>>(
        ah, woh, b_o, out, nullptr, MROWS, DMODEL, DMODEL);
}

// round 14
// speedup vs baseline: 3.5268x; 1.1546x over previous
#include <cuda_runtime.h>
#include <cuda_fp16.h>
#include <math.h>
#include <stdint.h>

// ---------------- problem constants ----------------
#define BATCH   2
#define SEQLEN  2048
#define DMODEL  4096
#define NHEADS  32
#define NKV     8
#define HD      128
#define QDIM    (NHEADS * HD)            // 4096
#define KVDIM   (NKV * HD)               // 1024
#define QKVDIM  (QDIM + 2 * KVDIM)       // 6144
#define MROWS   (BATCH * SEQLEN)         // 4096

// ---------------- scratch (device globals: allocation-free) ----------------
__device__ __half g_xh[(size_t)MROWS * DMODEL];
__device__ __half g_wqkvh[(size_t)QKVDIM * DMODEL];
__device__ __half g_woh[(size_t)DMODEL * DMODEL];
__device__ __half g_ah[(size_t)MROWS * DMODEL];
__device__ __half g_qh[(size_t)MROWS * QKVDIM];   // rope'd qkv (fp16)

// ---------------- helpers ----------------
__device__ __forceinline__ uint32_t smem_to_u32(const void* smem_ptr) {
    uint32_t addr;
    asm("{ .reg .u64 tmp; cvta.to.shared.u64 tmp, %1; cvt.u32.u64 %0, tmp; }"
        : "=r"(addr) : "l"(smem_ptr));
    return addr;
}
__device__ __forceinline__ void cp_async16(uint32_t dst, const void* src) {
    asm volatile("cp.async.cg.shared.global [%0], [%1], 16;\n"
                 :: "r"(dst), "l"(src));
}
__device__ __forceinline__ void cp_commit() {
    asm volatile("cp.async.commit_group;\n" ::: "memory");
}
__device__ __forceinline__ void cp_wait0() {
    asm volatile("cp.async.wait_group 0;\n" ::: "memory");
}
__device__ __forceinline__ void cp_wait1() {
    asm volatile("cp.async.wait_group 1;\n" ::: "memory");
}
__device__ __forceinline__ void ldm_x4(uint32_t* r, uint32_t a) {
    asm volatile("ldmatrix.sync.aligned.m8n8.x4.shared.b16 {%0,%1,%2,%3}, [%4];"
                 : "=r"(r[0]), "=r"(r[1]), "=r"(r[2]), "=r"(r[3]) : "r"(a));
}
__device__ __forceinline__ void ldm_x4_t(uint32_t* r, uint32_t a) {
    asm volatile("ldmatrix.sync.aligned.m8n8.x4.trans.shared.b16 {%0,%1,%2,%3}, [%4];"
                 : "=r"(r[0]), "=r"(r[1]), "=r"(r[2]), "=r"(r[3]) : "r"(a));
}
__device__ __forceinline__ void mma_fp16(float* c, const uint32_t* a,
                                         uint32_t b0, uint32_t b1) {
    asm volatile(
        "mma.sync.aligned.m16n8k16.row.col.f32.f16.f16.f32 "
        "{%0,%1,%2,%3}, {%4,%5,%6,%7}, {%8,%9}, {%0,%1,%2,%3};"
        : "+f"(c[0]), "+f"(c[1]), "+f"(c[2]), "+f"(c[3])
        : "r"(a[0]), "r"(a[1]), "r"(a[2]), "r"(a[3]), "r"(b0), "r"(b1));
}
__device__ __forceinline__ float ex2f(float x) {
    float y;
    asm("ex2.approx.f32 %0, %1;" : "=f"(y) : "f"(x));
    return y;
}
__device__ __forceinline__ uint32_t pack_fp16(float f0, float f1) {
    uint16_t b0 = __half_as_ushort(__float2half_rn(f0));
    uint16_t b1 = __half_as_ushort(__float2half_rn(f1));
    return ((uint32_t)b1 << 16) | (uint32_t)b0;
}

// ============================================================
// HMMA GEMM v6 (fp16): C = Ah[M,K] @ Bh[N,K]^T + bias
// 256 threads (8 warps 4x2, warp tile 32x32), CTA tile 128x64,
// BK=64, XOR-swizzled smem (no pad), 3-stage pipeline,
// 3 CTAs per SM.
// ============================================================
#define HBM 128
#define HBN 64
#define HBK 64
// row = 64 halves = 128 B, 8 chunks of 16B, swizzle: chunk ^= (row & 7)
#define OFF_B (128 * 128)               // 16384
#define STAGE_B ((128 + 64) * 128)      // 24576
#define HSMEM (3 * STAGE_B)             // 73728

__device__ __forceinline__ uint32_t sw_off(int row, int chunk) {
    return (uint32_t)(row * 128 + ((chunk ^ (row & 7)) << 4));
}

__device__ __forceinline__ void gemm_load_stage(
    const __half* __restrict__ Ah, const __half* __restrict__ Bh,
    uint32_t sbase, int bm, int bn, int k0, int K, int tid)
{
    // A: 128 rows x 8 chunks = 1024 -> 4 iters of 256
    #pragma unroll
    for (int l = 0; l < 4; l++) {
        int u = tid + l * 256;
        int r = u >> 3, g = u & 7;
        size_t goff = (size_t)(bm + r) * K + k0 + g * 8;
        cp_async16(sbase + sw_off(r, g), Ah + goff);
    }
    // B: 64 rows x 8 chunks = 512 -> 2 iters
    #pragma unroll
    for (int l = 0; l < 2; l++) {
        int u = tid + l * 256;
        int r = u >> 3, g = u & 7;
        size_t goff = (size_t)(bn + r) * K + k0 + g * 8;
        cp_async16(sbase + OFF_B + sw_off(r, g), Bh + goff);
    }
}

template <bool FUSE_ROPE>
__global__ __launch_bounds__(256, 3) void hmma_gemm_kernel(
    const __half* __restrict__ Ah, const __half* __restrict__ Bh,
    const float* __restrict__ bias,
    float* __restrict__ C32, __half* __restrict__ C16,
    int M, int N, int K)
{
    extern __shared__ char smem[];
    const uint32_t sb = smem_to_u32(smem);
    const int tid = threadIdx.x;
    const int lane = tid & 31, wid = tid >> 5;
    const int wm = wid & 3;        // 4 warp rows (32 m each)
    const int wn = wid >> 2;       // 2 warp cols (32 n each)
    const int bm = blockIdx.y * HBM;
    const int bn = blockIdx.x * HBN;

    float acc[2][4][4];
    #pragma unroll
    for (int i = 0; i < 2; i++)
        #pragma unroll
        for (int j = 0; j < 4; j++)
            #pragma unroll
            for (int v = 0; v < 4; v++) acc[i][j][v] = 0.f;

    const int NC = K / HBK;   // 64

    gemm_load_stage(Ah, Bh, sb, bm, bn, 0, K, tid);
    cp_commit();
    gemm_load_stage(Ah, Bh, sb + STAGE_B, bm, bn, HBK, K, tid);
    cp_commit();

    // per-lane ldmatrix row indices (constant across chunks)
    const int arow0 = wm * 32 + (lane & 15);        // + mt*16
    const int brow0 = wn * 32 + (lane & 15);        // + nb*16
    const int khalf = lane >> 4;                    // chunk sub-offset

    int st = 0;
    for (int c = 0; c < NC; c++) {
        if (c + 2 < NC) cp_wait1(); else cp_wait0();
        __syncthreads();

        if (c + 2 < NC) {
            int st2 = st + 2; if (st2 >= 3) st2 -= 3;
            gemm_load_stage(Ah, Bh, sb + st2 * STAGE_B,
                            bm, bn, (c + 2) * HBK, K, tid);
            cp_commit();
        }

        const uint32_t base = sb + st * STAGE_B;
        #pragma unroll
        for (int ks = 0; ks < 4; ks++) {
            const int chunk = ks * 2 + khalf;
            uint32_t A0[2][4], B0[2][4];
            #pragma unroll
            for (int mt = 0; mt < 2; mt++) {
                int r = arow0 + mt * 16;
                ldm_x4(A0[mt], base + sw_off(r, chunk));
            }
            #pragma unroll
            for (int nb = 0; nb < 2; nb++) {
                int r = brow0 + nb * 16;
                ldm_x4(B0[nb], base + OFF_B + sw_off(r, chunk));
            }
            #pragma unroll
            for (int mt = 0; mt < 2; mt++)
                #pragma unroll
                for (int nb = 0; nb < 2; nb++) {
                    mma_fp16(acc[mt][2 * nb],     A0[mt], B0[nb][0], B0[nb][2]);
                    mma_fp16(acc[mt][2 * nb + 1], A0[mt], B0[nb][1], B0[nb][3]);
                }
        }
        if (++st == 3) st = 0;
    }

    // ---------------- epilogue ----------------
    #pragma unroll
    for (int mt = 0; mt < 2; mt++) {
        const int row0 = bm + wm * 32 + mt * 16 + (lane >> 2);
        #pragma unroll
        for (int nt = 0; nt < 4; nt++) {
            const int col = bn + wn * 32 + nt * 8 + (lane & 3) * 2;
            const float b0 = bias[col], b1 = bias[col + 1];
            float a0 = acc[mt][nt][0] + b0, a1 = acc[mt][nt][1] + b1;
            float a2 = acc[mt][nt][2] + b0, a3 = acc[mt][nt][3] + b1;
            if (FUSE_ROPE) {
                if (col < QDIM + KVDIM) {
                    const int p = (col & 127) >> 1;
                    const float inv_freq =
                        exp2f(-(float)(2 * p) * (13.287712379549449f / 128.f));
                    {
                        float s = (float)(row0 & (SEQLEN - 1));
                        float cc, sn; sincosf(s * inv_freq, &sn, &cc);
                        float r0 = a0 * cc - a1 * sn;
                        float r1 = a0 * sn + a1 * cc;
                        a0 = r0; a1 = r1;
                    }
                    {
                        float s = (float)((row0 + 8) & (SEQLEN - 1));
                        float cc, sn; sincosf(s * inv_freq, &sn, &cc);
                        float r0 = a2 * cc - a3 * sn;
                        float r1 = a2 * sn + a3 * cc;
                        a2 = r0; a3 = r1;
                    }
                }
                *(uint32_t*)(C16 + (size_t)row0 * N + col) = pack_fp16(a0, a1);
                *(uint32_t*)(C16 + (size_t)(row0 + 8) * N + col) = pack_fp16(a2, a3);
            } else {
                *(float2*)(C32 + (size_t)row0 * N + col) = make_float2(a0, a1);
                *(float2*)(C32 + (size_t)(row0 + 8) * N + col) = make_float2(a2, a3);
            }
        }
    }
}

// ============================================================
// fp32 -> fp16 convert
// ============================================================
__global__ void convert_fp16_kernel(const float* __restrict__ src,
                                    __half* __restrict__ hi, int n4)
{
    int i = blockIdx.x * blockDim.x + threadIdx.x;
    if (i >= n4) return;
    float4 v = ((const float4*)src)[i];
    __half2* hp = (__half2*)hi;
    hp[2 * i]     = __halves2half2(__float2half_rn(v.x), __float2half_rn(v.y));
    hp[2 * i + 1] = __halves2half2(__float2half_rn(v.z), __float2half_rn(v.w));
}

// ============================================================
// HMMA flash attention (fp16 single-pass), 2 CTAs/SM:
// Br=128 (8 warps x 16 rows), Bc=64.
// scores = Qh·Kh ; O += Ph·Vh. Output -> fp16.
// ============================================================
#define QROWB 272
#define FA_QH  0
#define FA_ST0 34816
#define FA_STB 34816          // Kh + Vh per stage
#define FA_KH  0
#define FA_VH  17408
#define FA_SMEM (34816 + 2 * 34816)   // 104448

__global__ __launch_bounds__(256, 2) void fa_hmma_kernel(
    const __half* __restrict__ qh, __half* __restrict__ oh)
{
    extern __shared__ char smem[];
    const uint32_t sb = smem_to_u32(smem);
    const int tid = threadIdx.x;
    const int lane = tid & 31, w = tid >> 5;
    const int b = blockIdx.z, h = blockIdx.y, qb = blockIdx.x;
    const int kvh = h >> 2;
    const int q0 = qb * 128;
    const int rowbase = b * SEQLEN;

    // Q tile: 128 rows x 16 chunks = 2048 -> 8 iters
    #pragma unroll
    for (int l = 0; l < 8; l++) {
        int u = tid + l * 256;
        int r = (u >> 4) & 127;
        int ch = u & 15;
        const __half* src = qh +
            (size_t)(rowbase + q0 + r) * QKVDIM + h * HD + ch * 8;
        cp_async16(sb + FA_QH + r * QROWB + ch * 16, src);
    }
    // KV stage: Kh + Vh = 2048 chunks -> 8 iters
    auto load_kv = [&](int t, int s) {
        const int k0 = t * 64;
        const uint32_t stb = sb + FA_ST0 + s * FA_STB;
        #pragma unroll
        for (int l = 0; l < 8; l++) {
            int u = tid + l * 256;
            int sel = u >> 10;            // 0 Kh, 1 Vh
            int r = (u >> 4) & 63;
            int ch = u & 15;
            int gcol = sel ? (QDIM + KVDIM + kvh * HD) : (QDIM + kvh * HD);
            const __half* src = qh +
                (size_t)(rowbase + k0 + r) * QKVDIM + gcol + ch * 8;
            cp_async16(stb + sel * 17408 + r * QROWB + ch * 16, src);
        }
    };

    const int tmax = 2 * qb + 2;
    load_kv(0, 0);
    cp_commit();

    const float CEXP = 0.12751742f;       // (1/sqrt(128)) * log2(e)
    float m2[2] = {-1e30f, -1e30f};
    float l2[2] = {0.f, 0.f};
    float O[16][4];
    #pragma unroll
    for (int i = 0; i < 16; i++)
        #pragma unroll
        for (int v = 0; v < 4; v++) O[i][v] = 0.f;

    const int qrow0 = q0 + w * 16;

    for (int t = 0; t < tmax; t++) {
        if (t + 1 < tmax) load_kv(t + 1, (t + 1) & 1);
        cp_commit();
        cp_wait1();
        __syncthreads();

        const int k0 = t * 64;
        const uint32_t stb = sb + FA_ST0 + (t & 1) * FA_STB;

        if (k0 <= qrow0 + 15) {
            // ---------- scores S = Qh Kh^T ----------
            float S[8][4];
            #pragma unroll
            for (int i = 0; i < 8; i++)
                #pragma unroll
                for (int v = 0; v < 4; v++) S[i][v] = 0.f;

            const uint32_t qa = sb + FA_QH + (w * 16 + (lane & 15)) * QROWB +
                                ((lane >> 4) * 16);
            const uint32_t ka = stb + FA_KH + ((lane & 15)) * QROWB +
                                ((lane >> 4) * 16);
            #pragma unroll
            for (int kc = 0; kc < 8; kc++) {
                uint32_t A0[4];
                ldm_x4(A0, qa + kc * 32);
                #pragma unroll
                for (int g = 0; g < 4; g++) {
                    uint32_t B[4];
                    ldm_x4(B, ka + kc * 32 + g * 16 * QROWB);
                    mma_fp16(S[2 * g],     A0, B[0], B[2]);
                    mma_fp16(S[2 * g + 1], A0, B[1], B[3]);
                }
            }

            // ---------- causal mask ----------
            if (k0 + 63 > qrow0) {
                const int r0 = qrow0 + (lane >> 2);
                #pragma unroll
                for (int nt = 0; nt < 8; nt++) {
                    const int c0 = k0 + nt * 8 + (lane & 3) * 2;
                    if (c0     > r0)     S[nt][0] = -1e30f;
                    if (c0 + 1 > r0)     S[nt][1] = -1e30f;
                    if (c0     > r0 + 8) S[nt][2] = -1e30f;
                    if (c0 + 1 > r0 + 8) S[nt][3] = -1e30f;
                }
            }

            // ---------- online softmax ----------
            #pragma unroll
            for (int r = 0; r < 2; r++) {
                const int i0 = r * 2;
                float rmax = -1e30f;
                #pragma unroll
                for (int nt = 0; nt < 8; nt++)
                    rmax = fmaxf(rmax, fmaxf(S[nt][i0], S[nt][i0 + 1]));
                rmax = fmaxf(rmax, __shfl_xor_sync(0xffffffffu, rmax, 1));
                rmax = fmaxf(rmax, __shfl_xor_sync(0xffffffffu, rmax, 2));
                const float mnew = fmaxf(m2[r], rmax);
                const float corr = ex2f((m2[r] - mnew) * CEXP);
                m2[r] = mnew;
                float psum = 0.f;
                #pragma unroll
                for (int nt = 0; nt < 8; nt++) {
                    float p0 = ex2f((S[nt][i0]     - mnew) * CEXP);
                    float p1 = ex2f((S[nt][i0 + 1] - mnew) * CEXP);
                    S[nt][i0] = p0; S[nt][i0 + 1] = p1;
                    psum += p0 + p1;
                }
                psum += __shfl_xor_sync(0xffffffffu, psum, 1);
                psum += __shfl_xor_sync(0xffffffffu, psum, 2);
                l2[r] = l2[r] * corr + psum;
                #pragma unroll
                for (int nt = 0; nt < 16; nt++) {
                    O[nt][i0]     *= corr;
                    O[nt][i0 + 1] *= corr;
                }
            }

            // ---------- PV: O += Ph Vh ----------
            #pragma unroll
            for (int j = 0; j < 4; j++) {
                uint32_t Ph[4];
                #pragma unroll
                for (int q = 0; q < 2; q++) {
                    const int nt = 2 * j + q;
                    Ph[2 * q]     = pack_fp16(S[nt][0], S[nt][1]);
                    Ph[2 * q + 1] = pack_fp16(S[nt][2], S[nt][3]);
                }
                const int vrow = j * 16 + (lane & 7) + ((lane >> 3) & 1) * 8;
                #pragma unroll
                for (int n = 0; n < 8; n++) {
                    uint32_t va = stb + FA_VH + vrow * QROWB +
                                  (n * 16 + (lane >> 4) * 8) * 2;
                    uint32_t Bv[4];
                    ldm_x4_t(Bv, va);
                    mma_fp16(O[2 * n],     Ph, Bv[0], Bv[1]);
                    mma_fp16(O[2 * n + 1], Ph, Bv[2], Bv[3]);
                }
            }
        }
        __syncthreads();
    }

    // ---------- epilogue: normalize, convert to fp16 ----------
    #pragma unroll
    for (int r = 0; r < 2; r++) {
        float inv = 1.0f / l2[r];
        const int row = rowbase + qrow0 + (lane >> 2) + r * 8;
        const size_t off = (size_t)row * DMODEL + h * HD + (lane & 3) * 2;
        #pragma unroll
        for (int nt = 0; nt < 16; nt++) {
            float f0 = O[nt][2 * r] * inv;
            float f1 = O[nt][2 * r + 1] * inv;
            *(uint32_t*)(oh + off + nt * 8) = pack_fp16(f0, f1);
        }
    }
}

// ============================================================
// launch
// ============================================================
extern "C" void kernel_launch(void* const* d_in, const int* in_sizes, int n_in,
                              void* d_out, int out_size)
{
    (void)in_sizes; (void)n_in; (void)out_size;
    const float* x      = (const float*)d_in[0];
    const float* w_qkv  = (const float*)d_in[1];
    const float* b_qkv  = (const float*)d_in[2];
    const float* w_o    = (const float*)d_in[3];
    const float* b_o    = (const float*)d_in[4];
    float* out = (float*)d_out;

    __half *xh, *wqh, *woh, *ah, *qh;
    cudaGetSymbolAddress((void**)&xh,  g_xh);
    cudaGetSymbolAddress((void**)&wqh, g_wqkvh);
    cudaGetSymbolAddress((void**)&woh, g_woh);
    cudaGetSymbolAddress((void**)&ah,  g_ah);
    cudaGetSymbolAddress((void**)&qh,  g_qh);

    cudaFuncSetAttribute(hmma_gemm_kernel<true>,
                         cudaFuncAttributeMaxDynamicSharedMemorySize, HSMEM);
    cudaFuncSetAttribute(hmma_gemm_kernel<false>,
                         cudaFuncAttributeMaxDynamicSharedMemorySize, HSMEM);
    cudaFuncSetAttribute(fa_hmma_kernel,
                         cudaFuncAttributeMaxDynamicSharedMemorySize, FA_SMEM);

    // 0) convert x and weights to fp16
    {
        int n4 = (MROWS * DMODEL) / 4;
        convert_fp16_kernel<<<n4 / 256, 256>>>(x, xh, n4);
        int w4 = (QKVDIM * DMODEL) / 4;
        convert_fp16_kernel<<<w4 / 256, 256>>>(w_qkv, wqh, w4);
        int o4 = (DMODEL * DMODEL) / 4;
        convert_fp16_kernel<<<o4 / 256, 256>>>(w_o, woh, o4);
    }

    // 1) QKV projection + fused bias/RoPE/fp16 -> g_qh
    hmma_gemm_kernel<true><<<dim3(QKVDIM / HBN, MROWS / HBM), 256, HSMEM>>>(
        xh, wqh, b_qkv, nullptr, qh, MROWS, QKVDIM, DMODEL);

    // 2) fp16 flash attention -> g_ah (fp16)
    fa_hmma_kernel<<<dim3(SEQLEN / 128, NHEADS, BATCH), 256, FA_SMEM>>>(
        qh, ah);

    // 3) O projection (fp16) -> fp32 out
    hmma_gemm_kernel<false><<<dim3(DMODEL / HBN, MROWS / HBM), 256, HSMEM>>>(
        ah, woh, b_o, out, nullptr, MROWS, DMODEL, DMODEL);
}